// round 13
// baseline (speedup 1.0000x reference)
#include <cuda_runtime.h>
#include <cuda_fp16.h>
#include <math.h>
#include <cstdint>

#define BB   16
#define HIN  12
#define WIN  2500
#define QQ   100
#define GW   25
#define LL   300
#define LEN_KEEP 75
#define NTOK 76
#define DD   768
#define DH   384
#define NHD  12
#define HD   64
#define DEPTH 12
#define MLPD 3072
#define SCALE 0.125f
#define EPS_LN 1e-5f
#define MROWS (BB * NTOK)     // 1216
#define M_PAD 1280            // 10 tiles of 128

#define QWN  (DEPTH * 3 * DD * DD)
#define PWN  (DEPTH * DD * DD)
#define F1N  (DEPTH * MLPD * DD)
#define F2N  (DEPTH * DD * MLPD)

// ---------------- scratch (device globals; no allocation allowed) -----------
__device__ float g_hfull[BB * LL * DD];
__device__ float g_carry[M_PAD * DD];
__device__ float g_qkv[M_PAD * 3 * DD];
__device__ float g_att[BB * NHD * NTOK * NTOK];
__device__ int   g_idsk[BB * LEN_KEEP];
__device__ float g_m[BB * NTOK];
__device__ unsigned g_gmax;

// split activations (fp16 main + fp16 residual)
__device__ __half g_act1[M_PAD * DD],   g_act2[M_PAD * DD];
__device__ __half g_hid1[M_PAD * MLPD], g_hid2[M_PAD * MLPD];
// fp16-rounded weights (single term)
__device__ __half g_wq[QWN];
__device__ __half g_wp[PWN];
__device__ __half g_w1[F1N];
__device__ __half g_w2[F2N];

// monotone float<->uint encoding for atomicMax on floats
__device__ __forceinline__ unsigned fenc(float f) {
    unsigned u = __float_as_uint(f);
    return (u & 0x80000000u) ? ~u : (u | 0x80000000u);
}
__device__ __forceinline__ float fdec(unsigned u) {
    return (u & 0x80000000u) ? __uint_as_float(u & 0x7fffffffu) : __uint_as_float(~u);
}

// ---------------- asm helpers -------------------------------------------------
#define CP_ASYNC16(dst, src) \
    asm volatile("cp.async.cg.shared.global [%0], [%1], 16;" :: "r"(dst), "l"(src))
#define CP_COMMIT() asm volatile("cp.async.commit_group;" ::: "memory")
#define LDSM4(r0, r1, r2, r3, addr)                                          \
    asm volatile("ldmatrix.sync.aligned.m8n8.x4.shared.b16 {%0,%1,%2,%3}, [%4];" \
        : "=r"(r0), "=r"(r1), "=r"(r2), "=r"(r3) : "r"(addr))

__device__ __forceinline__ void mma_fp16(float* d, const uint32_t* a,
                                         uint32_t b0, uint32_t b1) {
    asm volatile(
        "mma.sync.aligned.m16n8k16.row.col.f32.f16.f16.f32 "
        "{%0,%1,%2,%3}, {%4,%5,%6,%7}, {%8,%9}, {%0,%1,%2,%3};"
        : "+f"(d[0]), "+f"(d[1]), "+f"(d[2]), "+f"(d[3])
        : "r"(a[0]), "r"(a[1]), "r"(a[2]), "r"(a[3]), "r"(b0), "r"(b1));
}

__device__ __forceinline__ uint32_t packh(float v0, float v1) {
    __half2 h = __floats2half2_rn(v0, v1);
    return *(uint32_t*)&h;
}
__device__ __forceinline__ uint32_t packh_big(float v0, float v1, float& r0, float& r1) {
    __half h0 = __float2half_rn(v0);
    __half h1 = __float2half_rn(v1);
    r0 = v0 - __half2float(h0);
    r1 = v1 - __half2float(h1);
    __half2 h = __halves2half2(h0, h1);
    return *(uint32_t*)&h;
}

// ---------------- merged weight round kernel (single launch) ------------------
__global__ void k_split_all(const float4* __restrict__ qw, const float4* __restrict__ pw,
                            const float4* __restrict__ f1, const float4* __restrict__ f2) {
    const int q4 = QWN / 4, p4 = PWN / 4, a4 = F1N / 4, b4 = F2N / 4;
    const int total = q4 + p4 + a4 + b4;
    for (int i = blockIdx.x * blockDim.x + threadIdx.x; i < total;
         i += gridDim.x * blockDim.x) {
        const float4* src;
        __half* dst;
        int j = i;
        if (j < q4)               { src = qw; dst = g_wq; }
        else if ((j -= q4) < p4)  { src = pw; dst = g_wp; }
        else if ((j -= p4) < a4)  { src = f1; dst = g_w1; }
        else { j -= a4;             src = f2; dst = g_w2; }
        float4 v = src[j];
        *(uint2*)&dst[(size_t)j * 4] = make_uint2(packh(v.x, v.y), packh(v.z, v.w));
    }
}

// ---------------- fp16 two-term pipelined GEMM --------------------------------
// C = (A1+A2)[M,K] @ W[N,K]^T + bias (+ops). Single barrier per chunk.
// BM=128, BK=32, 256 threads (8 warps: 4M x 2N). Warp tile 32 x BN/2.
// MODE 0: bias -> fp32 C ; MODE 1: bias+gelu -> split fp16 (C1,C2)
// MODE 2: bias+res -> fp32 C
template <int BN, int MODE, int NST, int MAXCTA>
__global__ void __launch_bounds__(256, MAXCTA)
k_gemm_f16(const __half* __restrict__ A1_g, const __half* __restrict__ A2_g,
           const __half* __restrict__ W_g,
           const float* __restrict__ bias, const float* __restrict__ res,
           float* __restrict__ C, __half* __restrict__ C1,
           __half* __restrict__ C2, int Ncols, int K) {
    extern __shared__ char sh[];
    const uint32_t STAGE = (256 + BN) * 80;       // bytes per stage
    const uint32_t AOFF = 128 * 80;
    uint32_t sbase = (uint32_t)__cvta_generic_to_shared(sh);

    const int tid = threadIdx.x;
    const int wid = tid >> 5, lane = tid & 31;
    const int g = lane >> 2, t = lane & 3;
    const int lrow = lane & 7, seg = lane >> 3;
    const int warp_m = wid & 3, warp_n = wid >> 2;
    const int wm0 = warp_m * 32;
    const int wn0 = warp_n * (BN / 2);
    const int m0 = blockIdx.y * 128, n0 = blockIdx.x * BN;
    const int NI = BN / 16;
    const int NCH = (256 + BN) * 4;
    const int nC = K >> 5;

    float acc[2][NI][4];
    #pragma unroll
    for (int mi = 0; mi < 2; mi++)
        #pragma unroll
        for (int ni = 0; ni < NI; ni++)
            #pragma unroll
            for (int j = 0; j < 4; j++) acc[mi][ni][j] = 0.f;

    auto load = [&](int c) {
        int k0 = c << 5;
        uint32_t base = sbase + (uint32_t)(c % NST) * STAGE;
        #pragma unroll
        for (int i = tid; i < NCH; i += 256) {
            const __half* gsrc;
            uint32_t dst;
            if (i < 512) {
                int row = i >> 2, j = i & 3;
                gsrc = A1_g + (size_t)(m0 + row) * K + k0 + j * 8;
                dst = base + row * 80 + j * 16;
            } else if (i < 1024) {
                int i2 = i - 512;
                int row = i2 >> 2, j = i2 & 3;
                gsrc = A2_g + (size_t)(m0 + row) * K + k0 + j * 8;
                dst = base + AOFF + row * 80 + j * 16;
            } else {
                int i2 = i - 1024;
                int row = i2 >> 2, j = i2 & 3;
                gsrc = W_g + (size_t)(n0 + row) * K + k0 + j * 8;
                dst = base + 2 * AOFF + row * 80 + j * 16;
            }
            CP_ASYNC16(dst, gsrc);
        }
        CP_COMMIT();
    };

    #pragma unroll
    for (int s = 0; s < NST - 1; s++) load(s);

    for (int c = 0; c < nC; c++) {
        if (c + NST - 1 < nC) {
            asm volatile("cp.async.wait_group %0;" :: "n"(NST - 2));
        } else {
            asm volatile("cp.async.wait_group 0;" ::: "memory");
        }
        __syncthreads();
        if (c + NST - 1 < nC) load(c + NST - 1);

        uint32_t base = sbase + (uint32_t)(c % NST) * STAGE;
        uint32_t a1B = base, a2B = base + AOFF;
        uint32_t wB = base + 2 * AOFF;

        #pragma unroll
        for (int ks = 0; ks < 2; ks++) {
            uint32_t x[2][4], y[2][4];
            #pragma unroll
            for (int mi = 0; mi < 2; mi++) {
                uint32_t off = (uint32_t)((wm0 + mi * 16 + (seg & 1) * 8 + lrow) * 80
                                          + ks * 32 + (seg >> 1) * 16);
                LDSM4(x[mi][0], x[mi][1], x[mi][2], x[mi][3], a1B + off);
                LDSM4(y[mi][0], y[mi][1], y[mi][2], y[mi][3], a2B + off);
            }
            #pragma unroll
            for (int np = 0; np < NI / 2; np++) {
                uint32_t off = (uint32_t)((wn0 + np * 16 + (seg >> 1) * 8 + lrow) * 80
                                          + ks * 32 + (seg & 1) * 16);
                uint32_t w0, w1, w2, w3;
                LDSM4(w0, w1, w2, w3, wB + off);
                int n1 = 2 * np, n2 = 2 * np + 1;
                #pragma unroll
                for (int mi = 0; mi < 2; mi++) mma_fp16(acc[mi][n1], x[mi], w0, w1);
                #pragma unroll
                for (int mi = 0; mi < 2; mi++) mma_fp16(acc[mi][n2], x[mi], w2, w3);
                #pragma unroll
                for (int mi = 0; mi < 2; mi++) mma_fp16(acc[mi][n1], y[mi], w0, w1);
                #pragma unroll
                for (int mi = 0; mi < 2; mi++) mma_fp16(acc[mi][n2], y[mi], w2, w3);
            }
        }
    }

    // epilogue
    #pragma unroll
    for (int mi = 0; mi < 2; mi++) {
        int r0 = m0 + wm0 + mi * 16 + g;
        int r1 = r0 + 8;
        #pragma unroll
        for (int ni = 0; ni < NI; ni++) {
            int n = n0 + wn0 + ni * 8 + 2 * t;
            float b0 = bias[n], b1 = bias[n + 1];
            float v0 = acc[mi][ni][0] + b0;
            float v1 = acc[mi][ni][1] + b1;
            float v2 = acc[mi][ni][2] + b0;
            float v3 = acc[mi][ni][3] + b1;
            if (MODE == 1) {
                v0 = 0.5f * v0 * (1.f + erff(v0 * 0.70710678118654752f));
                v1 = 0.5f * v1 * (1.f + erff(v1 * 0.70710678118654752f));
                v2 = 0.5f * v2 * (1.f + erff(v2 * 0.70710678118654752f));
                v3 = 0.5f * v3 * (1.f + erff(v3 * 0.70710678118654752f));
                float s0, s1, s2, s3;
                uint32_t m0w = packh_big(v0, v1, s0, s1);
                uint32_t m1w = packh_big(v2, v3, s2, s3);
                *(uint32_t*)&C1[(size_t)r0 * Ncols + n] = m0w;
                *(uint32_t*)&C1[(size_t)r1 * Ncols + n] = m1w;
                *(uint32_t*)&C2[(size_t)r0 * Ncols + n] = packh(s0, s1);
                *(uint32_t*)&C2[(size_t)r1 * Ncols + n] = packh(s2, s3);
            } else {
                if (MODE == 2) {
                    v0 += res[(size_t)r0 * Ncols + n];
                    v1 += res[(size_t)r0 * Ncols + n + 1];
                    v2 += res[(size_t)r1 * Ncols + n];
                    v3 += res[(size_t)r1 * Ncols + n + 1];
                }
                *(float2*)&C[(size_t)r0 * Ncols + n] = make_float2(v0, v1);
                *(float2*)&C[(size_t)r1 * Ncols + n] = make_float2(v2, v3);
            }
        }
    }
}

// ---------------- fused patchify + select (one launch) ------------------------
__global__ void k_patchsel(const float* __restrict__ x,
                           const float* __restrict__ attn_mask,
                           const int*   __restrict__ yids,
                           const float* __restrict__ conv_w,
                           const float* __restrict__ conv_b,
                           const float* __restrict__ pex,
                           const float* __restrict__ ytab,
                           const float* __restrict__ noise) {
    if (blockIdx.x >= BB * LL) {
        int b = blockIdx.x - BB * LL;
        __shared__ float ns[LL];
        __shared__ int ids[LL];
        __shared__ unsigned char keep[LL];
        for (int i = threadIdx.x; i < LL; i += blockDim.x) { ns[i] = noise[b * LL + i]; keep[i] = 0; }
        __syncthreads();
        for (int i = threadIdx.x; i < LL; i += blockDim.x) {
            float vi = ns[i];
            int r = 0;
            for (int j = 0; j < LL; j++) {
                float vj = ns[j];
                r += (vj < vi) || (vj == vi && j < i);
            }
            ids[r] = i;
        }
        __syncthreads();
        for (int t = threadIdx.x; t < LEN_KEEP; t += blockDim.x) {
            g_idsk[b * LEN_KEEP + t] = ids[t];
            keep[ids[t]] = 1;
        }
        __syncthreads();
        for (int i = threadIdx.x; i < LL; i += blockDim.x) {
            if (keep[i]) {
                int pos = 0;
                for (int j = 0; j < i; j++) pos += keep[j];
                g_m[b * NTOK + 1 + pos] = attn_mask[b * LL + i];
            }
        }
        if (threadIdx.x == 0) g_m[b * NTOK] = 1.f;
        return;
    }
    int bl = blockIdx.x;
    int b = bl / LL, l = bl % LL;
    int gh = l / GW, gw = l % GW;
    __shared__ float patch[QQ];
    const float* xrow = x + ((size_t)b * HIN + gh) * WIN + gw * QQ;
    for (int i = threadIdx.x; i < QQ; i += blockDim.x) patch[i] = xrow[i];
    __syncthreads();
    float am = attn_mask[b * LL + l];
    int yid = yids[b * LL + l];
    for (int d = threadIdx.x; d < DD; d += blockDim.x) {
        const float* w = conv_w + d * QQ;
        float acc = 0.f;
        #pragma unroll 4
        for (int q = 0; q < QQ; q++) acc += patch[q] * w[q];
        acc += conv_b[d];
        if (d < DH) acc += ytab[yid * DH + d];
        else        acc += am * pex[(gw + 1) * DH + (d - DH)];
        g_hfull[((size_t)b * LL + l) * DD + d] = acc;
    }
}

// ---------------- fused gather + layer-0 LN1 (split fp16) + gmax reset --------
__global__ void k_gather_ln(const float* __restrict__ cls_token,
                            const float* __restrict__ pex,
                            const float* __restrict__ w,
                            const float* __restrict__ bias) {
    int bt = blockIdx.x;
    int b = bt / NTOK, t = bt % NTOK;
    if (bt == 0 && threadIdx.x == 0) g_gmax = 0u;
    __shared__ float row[DD];
    __shared__ float red[256];
    float* outp = g_carry + (size_t)bt * DD;
    if (t == 0) {
        for (int d = threadIdx.x; d < DD; d += 256) {
            float v = cls_token[d] + (d >= DH ? pex[d - DH] : 0.f);
            row[d] = v; outp[d] = v;
        }
    } else {
        int l = g_idsk[b * LEN_KEEP + (t - 1)];
        const float* src = g_hfull + ((size_t)b * LL + l) * DD;
        for (int d = threadIdx.x; d < DD; d += 256) {
            float v = src[d];
            row[d] = v; outp[d] = v;
        }
    }
    __syncthreads();
    float s = 0.f;
    for (int d = threadIdx.x; d < DD; d += 256) s += row[d];
    red[threadIdx.x] = s; __syncthreads();
    for (int o = 128; o > 0; o >>= 1) {
        if (threadIdx.x < o) red[threadIdx.x] += red[threadIdx.x + o];
        __syncthreads();
    }
    float mu = red[0] * (1.f / DD);
    __syncthreads();
    float v = 0.f;
    for (int d = threadIdx.x; d < DD; d += 256) { float u = row[d] - mu; v += u * u; }
    red[threadIdx.x] = v; __syncthreads();
    for (int o = 128; o > 0; o >>= 1) {
        if (threadIdx.x < o) red[threadIdx.x] += red[threadIdx.x + o];
        __syncthreads();
    }
    float rstd = rsqrtf(red[0] * (1.f / DD) + EPS_LN);
    for (int d = threadIdx.x; d < DD; d += 256) {
        float val = (row[d] - mu) * rstd * w[d] + bias[d];
        __half h = __float2half_rn(val);
        g_act1[(size_t)bt * DD + d] = h;
        g_act2[(size_t)bt * DD + d] = __float2half_rn(val - __half2float(h));
    }
}

// ---------------- layernorm (fp32 out, final) ---------------------------------
__global__ void k_ln(const float* __restrict__ in,
                     const float* __restrict__ w,
                     const float* __restrict__ bias,
                     float* __restrict__ out) {
    int r = blockIdx.x;
    const float* p = in + (size_t)r * DD;
    __shared__ float red[256];
    float s = 0.f;
    for (int d = threadIdx.x; d < DD; d += 256) s += p[d];
    red[threadIdx.x] = s; __syncthreads();
    for (int o = 128; o > 0; o >>= 1) {
        if (threadIdx.x < o) red[threadIdx.x] += red[threadIdx.x + o];
        __syncthreads();
    }
    float mu = red[0] * (1.f / DD);
    __syncthreads();
    float v = 0.f;
    for (int d = threadIdx.x; d < DD; d += 256) { float t = p[d] - mu; v += t * t; }
    red[threadIdx.x] = v; __syncthreads();
    for (int o = 128; o > 0; o >>= 1) {
        if (threadIdx.x < o) red[threadIdx.x] += red[threadIdx.x + o];
        __syncthreads();
    }
    float rstd = rsqrtf(red[0] * (1.f / DD) + EPS_LN);
    for (int d = threadIdx.x; d < DD; d += 256)
        out[(size_t)r * DD + d] = (p[d] - mu) * rstd * w[d] + bias[d];
}

// ---------------- layernorm (split fp16 out; also resets g_gmax) --------------
__global__ void k_ln_sp(const float* __restrict__ in,
                        const float* __restrict__ w,
                        const float* __restrict__ bias) {
    int r = blockIdx.x;
    if (r == 0 && threadIdx.x == 0) g_gmax = 0u;
    const float* p = in + (size_t)r * DD;
    __shared__ float red[256];
    float s = 0.f;
    for (int d = threadIdx.x; d < DD; d += 256) s += p[d];
    red[threadIdx.x] = s; __syncthreads();
    for (int o = 128; o > 0; o >>= 1) {
        if (threadIdx.x < o) red[threadIdx.x] += red[threadIdx.x + o];
        __syncthreads();
    }
    float mu = red[0] * (1.f / DD);
    __syncthreads();
    float v = 0.f;
    for (int d = threadIdx.x; d < DD; d += 256) { float t = p[d] - mu; v += t * t; }
    red[threadIdx.x] = v; __syncthreads();
    for (int o = 128; o > 0; o >>= 1) {
        if (threadIdx.x < o) red[threadIdx.x] += red[threadIdx.x + o];
        __syncthreads();
    }
    float rstd = rsqrtf(red[0] * (1.f / DD) + EPS_LN);
    for (int d = threadIdx.x; d < DD; d += 256) {
        float val = (p[d] - mu) * rstd * w[d] + bias[d];
        __half h = __float2half_rn(val);
        g_act1[(size_t)r * DD + d] = h;
        g_act2[(size_t)r * DD + d] = __float2half_rn(val - __half2float(h));
    }
}

// ---------------- attention scores: one block per (b,h) -----------------------
__global__ void __launch_bounds__(256)
k_scores_bh() {
    int bh = blockIdx.x;
    int h = bh % NHD, b = bh / NHD;
    __shared__ float Qsh[NTOK][65];
    __shared__ float Ksh[NTOK][65];
    __shared__ float msh[NTOK];
    __shared__ float wmax[8];
    int tid = threadIdx.x;
    for (int idx = tid; idx < NTOK * HD; idx += 256) {
        int r = idx >> 6, d = idx & 63;
        size_t base = (size_t)(b * NTOK + r) * (3 * DD) + h * HD + d;
        Qsh[r][d] = g_qkv[base];
        Ksh[r][d] = g_qkv[base + DD];
    }
    for (int i = tid; i < NTOK; i += 256) msh[i] = g_m[b * NTOK + i];
    __syncthreads();
    int w = tid >> 5, lane = tid & 31;
    float lmax = -3.4e38f;
    for (int n = w; n < NTOK; n += 8) {
        float mn = msh[n];
        float* outrow = &g_att[((size_t)bh * NTOK + n) * NTOK];
        for (int m = lane; m < NTOK; m += 32) {
            float dot = 0.f;
            #pragma unroll
            for (int d = 0; d < HD; d++) dot += Qsh[n][d] * Ksh[m][d];
            float logit = dot * SCALE;
            if (mn * msh[m] == 0.f) logit = -INFINITY;
            else lmax = fmaxf(lmax, logit);
            outrow[m] = logit;
        }
    }
    #pragma unroll
    for (int o = 16; o > 0; o >>= 1)
        lmax = fmaxf(lmax, __shfl_xor_sync(0xffffffffu, lmax, o));
    if (lane == 0) wmax[w] = lmax;
    __syncthreads();
    if (tid == 0) {
        float bm = wmax[0];
        #pragma unroll
        for (int i = 1; i < 8; i++) bm = fmaxf(bm, wmax[i]);
        if (bm > -3.3e38f) atomicMax(&g_gmax, fenc(bm));
    }
}

// ---------------- softmax + AV: one block per (b,h) -> split fp16 --------------
__global__ void __launch_bounds__(256)
k_softmax_bh() {
    int bh = blockIdx.x;
    int h = bh % NHD, b = bh / NHD;
    __shared__ float Vsh[NTOK][65];
    __shared__ float Psh[NTOK][77];
    __shared__ float rsum[NTOK];
    int tid = threadIdx.x;
    for (int idx = tid; idx < NTOK * HD; idx += 256) {
        int r = idx >> 6, d = idx & 63;
        Vsh[r][d] = g_qkv[(size_t)(b * NTOK + r) * (3 * DD) + 2 * DD + h * HD + d];
    }
    __syncthreads();
    int w = tid >> 5, lane = tid & 31;
    float gmx = fdec(g_gmax);
    for (int n = w; n < NTOK; n += 8) {
        const float* arow = &g_att[((size_t)bh * NTOK + n) * NTOK];
        float s = 0.f;
        for (int m = lane; m < NTOK; m += 32) {
            float e = expf(arow[m] - gmx);
            Psh[n][m] = e;
            s += e;
        }
        #pragma unroll
        for (int o = 16; o > 0; o >>= 1) s += __shfl_xor_sync(0xffffffffu, s, o);
        if (lane == 0) rsum[n] = s;
    }
    __syncthreads();
    for (int n = w; n < NTOK; n += 8) {
        float inv = 1.f / (rsum[n] + 1e-9f);
        for (int d = lane; d < HD; d += 32) {
            float acc = 0.f;
            for (int m = 0; m < NTOK; m++) acc += Psh[n][m] * Vsh[m][d];
            float val = acc * inv;
            __half hv = __float2half_rn(val);
            size_t o2 = (size_t)(b * NTOK + n) * DD + h * HD + d;
            g_act1[o2] = hv;
            g_act2[o2] = __float2half_rn(val - __half2float(hv));
        }
    }
}

// ---------------- launch -----------------------------------------------------
extern "C" void kernel_launch(void* const* d_in, const int* in_sizes, int n_in,
                              void* d_out, int out_size) {
    const float* x         = (const float*)d_in[0];
    const float* attn_mask = (const float*)d_in[1];
    const int*   yids      = (const int*)  d_in[2];
    const float* noise     = (const float*)d_in[3];
    const float* conv_w    = (const float*)d_in[4];
    const float* conv_b    = (const float*)d_in[5];
    const float* pex       = (const float*)d_in[6];
    const float* ytab      = (const float*)d_in[7];
    const float* cls       = (const float*)d_in[8];
    const float* qkv_w     = (const float*)d_in[9];
    const float* qkv_b     = (const float*)d_in[10];
    const float* proj_w    = (const float*)d_in[11];
    const float* proj_b    = (const float*)d_in[12];
    const float* ln1_w     = (const float*)d_in[13];
    const float* ln1_b     = (const float*)d_in[14];
    const float* ln2_w     = (const float*)d_in[15];
    const float* ln2_b     = (const float*)d_in[16];
    const float* fc1_w     = (const float*)d_in[17];
    const float* fc1_b     = (const float*)d_in[18];
    const float* fc2_w     = (const float*)d_in[19];
    const float* fc2_b     = (const float*)d_in[20];
    const float* norm_w    = (const float*)d_in[21];
    const float* norm_b    = (const float*)d_in[22];
    float* out = (float*)d_out;

    float *carry, *qkv;
    __half *act1, *act2, *hid1, *hid2, *wq, *wp, *w1, *w2;
    cudaGetSymbolAddress((void**)&carry, g_carry);
    cudaGetSymbolAddress((void**)&qkv,   g_qkv);
    cudaGetSymbolAddress((void**)&act1,  g_act1);
    cudaGetSymbolAddress((void**)&act2,  g_act2);
    cudaGetSymbolAddress((void**)&hid1,  g_hid1);
    cudaGetSymbolAddress((void**)&hid2,  g_hid2);
    cudaGetSymbolAddress((void**)&wq,    g_wq);
    cudaGetSymbolAddress((void**)&wp,    g_wp);
    cudaGetSymbolAddress((void**)&w1,    g_w1);
    cudaGetSymbolAddress((void**)&w2,    g_w2);

    const int SM96  = 3 * (256 + 96)  * 80;  // 84480  -> 2 CTAs/SM
    const int SM128 = 3 * (256 + 128) * 80;  // 92160  -> 2 CTAs/SM
    const int SM32  = 4 * (256 + 32)  * 80;  // 92160  -> 2 CTAs/SM
    cudaFuncSetAttribute(k_gemm_f16<96, 0, 3, 2>,  cudaFuncAttributeMaxDynamicSharedMemorySize, SM96);
    cudaFuncSetAttribute(k_gemm_f16<128, 1, 3, 2>, cudaFuncAttributeMaxDynamicSharedMemorySize, SM128);
    cudaFuncSetAttribute(k_gemm_f16<32, 2, 4, 2>,  cudaFuncAttributeMaxDynamicSharedMemorySize, SM32);

    const int MT = M_PAD / 128;  // 10

    // #1 weight fp16 rounding
    k_split_all<<<4096, 256>>>((const float4*)qkv_w, (const float4*)proj_w,
                               (const float4*)fc1_w, (const float4*)fc2_w);
    // #2 fused patchify + select
    k_patchsel<<<BB * LL + BB, 256>>>(x, attn_mask, yids, conv_w, conv_b, pex, ytab, noise);
    // #3 fused gather + layer-0 LN1 + gmax reset
    k_gather_ln<<<MROWS, 256>>>(cls, pex, ln1_w, ln1_b);

    for (int l = 0; l < DEPTH; l++) {
        const float* qb  = qkv_b  + (size_t)l * 3 * DD;
        const float* pb  = proj_b + (size_t)l * DD;
        const float* l1w = ln1_w + l * DD; const float* l1b = ln1_b + l * DD;
        const float* l2w = ln2_w + l * DD; const float* l2b = ln2_b + l * DD;
        const float* f1b = fc1_b + (size_t)l * MLPD;
        const float* f2b = fc2_b + (size_t)l * DD;
        __half* lwq = wq + (size_t)l * 3 * DD * DD;
        __half* lwp = wp + (size_t)l * DD * DD;
        __half* lw1 = w1 + (size_t)l * MLPD * DD;
        __half* lw2 = w2 + (size_t)l * DD * MLPD;

        if (l > 0) k_ln_sp<<<MROWS, 256>>>(carry, l1w, l1b);
        // qkv: 24x10 = 240 CTAs, 2/SM
        k_gemm_f16<96, 0, 3, 2><<<dim3(3 * DD / 96, MT), 256, SM96>>>(
            act1, act2, lwq, qb, nullptr, qkv, nullptr, nullptr, 3 * DD, DD);
        k_scores_bh<<<BB * NHD, 256>>>();
        k_softmax_bh<<<BB * NHD, 256>>>();
        // proj: 24x10 = 240 CTAs, 2/SM
        k_gemm_f16<32, 2, 4, 2><<<dim3(DD / 32, MT), 256, SM32>>>(
            act1, act2, lwp, pb, carry, carry, nullptr, nullptr, DD, DD);
        k_ln_sp<<<MROWS, 256>>>(carry, l2w, l2b);
        // fc1: 24x10 = 240 CTAs, 2/SM
        k_gemm_f16<128, 1, 3, 2><<<dim3(MLPD / 128, MT), 256, SM128>>>(
            act1, act2, lw1, f1b, nullptr, nullptr, hid1, hid2, MLPD, DD);
        // fc2: 24x10 = 240 CTAs, 2/SM
        k_gemm_f16<32, 2, 4, 2><<<dim3(DD / 32, MT), 256, SM32>>>(
            hid1, hid2, lw2, f2b, carry, carry, nullptr, nullptr, DD, MLPD);
    }

    k_ln<<<MROWS, 256>>>(carry, norm_w, norm_b, out);
}

// round 14
// speedup vs baseline: 1.1143x; 1.1143x over previous
#include <cuda_runtime.h>
#include <cuda_fp16.h>
#include <math.h>
#include <cstdint>

#define BB   16
#define HIN  12
#define WIN  2500
#define QQ   100
#define GW   25
#define LL   300
#define LEN_KEEP 75
#define NTOK 76
#define DD   768
#define DH   384
#define NHD  12
#define HD   64
#define DEPTH 12
#define MLPD 3072
#define SCALE 0.125f
#define EPS_LN 1e-5f
#define MROWS (BB * NTOK)     // 1216
#define M_PAD 1280            // 10 tiles of 128

#define QWN  (DEPTH * 3 * DD * DD)
#define PWN  (DEPTH * DD * DD)
#define F1N  (DEPTH * MLPD * DD)
#define F2N  (DEPTH * DD * MLPD)

// ---------------- scratch (device globals; no allocation allowed) -----------
__device__ float g_hfull[BB * LL * DD];
__device__ float g_carry[M_PAD * DD];
__device__ float g_qkv[M_PAD * 3 * DD];
__device__ float g_att[BB * NHD * NTOK * NTOK];
__device__ int   g_idsk[BB * LEN_KEEP];
__device__ float g_m[BB * NTOK];
__device__ unsigned g_gmax;

// split activations (fp16 main + fp16 residual)
__device__ __half g_act1[M_PAD * DD],   g_act2[M_PAD * DD];
__device__ __half g_hid1[M_PAD * MLPD], g_hid2[M_PAD * MLPD];
// fp16-rounded weights (single term)
__device__ __half g_wq[QWN];
__device__ __half g_wp[PWN];
__device__ __half g_w1[F1N];
__device__ __half g_w2[F2N];

// monotone float<->uint encoding for atomicMax on floats
__device__ __forceinline__ unsigned fenc(float f) {
    unsigned u = __float_as_uint(f);
    return (u & 0x80000000u) ? ~u : (u | 0x80000000u);
}
__device__ __forceinline__ float fdec(unsigned u) {
    return (u & 0x80000000u) ? __uint_as_float(u & 0x7fffffffu) : __uint_as_float(~u);
}

// ---------------- asm helpers -------------------------------------------------
#define CP_ASYNC16(dst, src) \
    asm volatile("cp.async.cg.shared.global [%0], [%1], 16;" :: "r"(dst), "l"(src))
#define CP_COMMIT() asm volatile("cp.async.commit_group;" ::: "memory")
#define LDSM4(r0, r1, r2, r3, addr)                                          \
    asm volatile("ldmatrix.sync.aligned.m8n8.x4.shared.b16 {%0,%1,%2,%3}, [%4];" \
        : "=r"(r0), "=r"(r1), "=r"(r2), "=r"(r3) : "r"(addr))

__device__ __forceinline__ void mma_fp16(float* d, const uint32_t* a,
                                         uint32_t b0, uint32_t b1) {
    asm volatile(
        "mma.sync.aligned.m16n8k16.row.col.f32.f16.f16.f32 "
        "{%0,%1,%2,%3}, {%4,%5,%6,%7}, {%8,%9}, {%0,%1,%2,%3};"
        : "+f"(d[0]), "+f"(d[1]), "+f"(d[2]), "+f"(d[3])
        : "r"(a[0]), "r"(a[1]), "r"(a[2]), "r"(a[3]), "r"(b0), "r"(b1));
}

__device__ __forceinline__ uint32_t packh(float v0, float v1) {
    __half2 h = __floats2half2_rn(v0, v1);
    return *(uint32_t*)&h;
}
__device__ __forceinline__ uint32_t packh_big(float v0, float v1, float& r0, float& r1) {
    __half h0 = __float2half_rn(v0);
    __half h1 = __float2half_rn(v1);
    r0 = v0 - __half2float(h0);
    r1 = v1 - __half2float(h1);
    __half2 h = __halves2half2(h0, h1);
    return *(uint32_t*)&h;
}

// ---------------- merged weight round kernel (single launch) ------------------
__global__ void k_split_all(const float4* __restrict__ qw, const float4* __restrict__ pw,
                            const float4* __restrict__ f1, const float4* __restrict__ f2) {
    const int q4 = QWN / 4, p4 = PWN / 4, a4 = F1N / 4, b4 = F2N / 4;
    const int total = q4 + p4 + a4 + b4;
    for (int i = blockIdx.x * blockDim.x + threadIdx.x; i < total;
         i += gridDim.x * blockDim.x) {
        const float4* src;
        __half* dst;
        int j = i;
        if (j < q4)               { src = qw; dst = g_wq; }
        else if ((j -= q4) < p4)  { src = pw; dst = g_wp; }
        else if ((j -= p4) < a4)  { src = f1; dst = g_w1; }
        else { j -= a4;             src = f2; dst = g_w2; }
        float4 v = src[j];
        *(uint2*)&dst[(size_t)j * 4] = make_uint2(packh(v.x, v.y), packh(v.z, v.w));
    }
}

// ---------------- fp16 two-term pipelined GEMM --------------------------------
template <int BN, int MODE, int NST, int MAXCTA>
__global__ void __launch_bounds__(256, MAXCTA)
k_gemm_f16(const __half* __restrict__ A1_g, const __half* __restrict__ A2_g,
           const __half* __restrict__ W_g,
           const float* __restrict__ bias, const float* __restrict__ res,
           float* __restrict__ C, __half* __restrict__ C1,
           __half* __restrict__ C2, int Ncols, int K) {
    extern __shared__ char sh[];
    const uint32_t STAGE = (256 + BN) * 80;
    const uint32_t AOFF = 128 * 80;
    uint32_t sbase = (uint32_t)__cvta_generic_to_shared(sh);

    const int tid = threadIdx.x;
    const int wid = tid >> 5, lane = tid & 31;
    const int g = lane >> 2, t = lane & 3;
    const int lrow = lane & 7, seg = lane >> 3;
    const int warp_m = wid & 3, warp_n = wid >> 2;
    const int wm0 = warp_m * 32;
    const int wn0 = warp_n * (BN / 2);
    const int m0 = blockIdx.y * 128, n0 = blockIdx.x * BN;
    const int NI = BN / 16;
    const int NCH = (256 + BN) * 4;
    const int nC = K >> 5;

    float acc[2][NI][4];
    #pragma unroll
    for (int mi = 0; mi < 2; mi++)
        #pragma unroll
        for (int ni = 0; ni < NI; ni++)
            #pragma unroll
            for (int j = 0; j < 4; j++) acc[mi][ni][j] = 0.f;

    auto load = [&](int c) {
        int k0 = c << 5;
        uint32_t base = sbase + (uint32_t)(c % NST) * STAGE;
        #pragma unroll
        for (int i = tid; i < NCH; i += 256) {
            const __half* gsrc;
            uint32_t dst;
            if (i < 512) {
                int row = i >> 2, j = i & 3;
                gsrc = A1_g + (size_t)(m0 + row) * K + k0 + j * 8;
                dst = base + row * 80 + j * 16;
            } else if (i < 1024) {
                int i2 = i - 512;
                int row = i2 >> 2, j = i2 & 3;
                gsrc = A2_g + (size_t)(m0 + row) * K + k0 + j * 8;
                dst = base + AOFF + row * 80 + j * 16;
            } else {
                int i2 = i - 1024;
                int row = i2 >> 2, j = i2 & 3;
                gsrc = W_g + (size_t)(n0 + row) * K + k0 + j * 8;
                dst = base + 2 * AOFF + row * 80 + j * 16;
            }
            CP_ASYNC16(dst, gsrc);
        }
        CP_COMMIT();
    };

    #pragma unroll
    for (int s = 0; s < NST - 1; s++) load(s);

    for (int c = 0; c < nC; c++) {
        if (c + NST - 1 < nC) {
            asm volatile("cp.async.wait_group %0;" :: "n"(NST - 2));
        } else {
            asm volatile("cp.async.wait_group 0;" ::: "memory");
        }
        __syncthreads();
        if (c + NST - 1 < nC) load(c + NST - 1);

        uint32_t base = sbase + (uint32_t)(c % NST) * STAGE;
        uint32_t a1B = base, a2B = base + AOFF;
        uint32_t wB = base + 2 * AOFF;

        #pragma unroll
        for (int ks = 0; ks < 2; ks++) {
            uint32_t x[2][4], y[2][4];
            #pragma unroll
            for (int mi = 0; mi < 2; mi++) {
                uint32_t off = (uint32_t)((wm0 + mi * 16 + (seg & 1) * 8 + lrow) * 80
                                          + ks * 32 + (seg >> 1) * 16);
                LDSM4(x[mi][0], x[mi][1], x[mi][2], x[mi][3], a1B + off);
                LDSM4(y[mi][0], y[mi][1], y[mi][2], y[mi][3], a2B + off);
            }
            #pragma unroll
            for (int np = 0; np < NI / 2; np++) {
                uint32_t off = (uint32_t)((wn0 + np * 16 + (seg >> 1) * 8 + lrow) * 80
                                          + ks * 32 + (seg & 1) * 16);
                uint32_t w0, w1, w2, w3;
                LDSM4(w0, w1, w2, w3, wB + off);
                int n1 = 2 * np, n2 = 2 * np + 1;
                #pragma unroll
                for (int mi = 0; mi < 2; mi++) mma_fp16(acc[mi][n1], x[mi], w0, w1);
                #pragma unroll
                for (int mi = 0; mi < 2; mi++) mma_fp16(acc[mi][n2], x[mi], w2, w3);
                #pragma unroll
                for (int mi = 0; mi < 2; mi++) mma_fp16(acc[mi][n1], y[mi], w0, w1);
                #pragma unroll
                for (int mi = 0; mi < 2; mi++) mma_fp16(acc[mi][n2], y[mi], w2, w3);
            }
        }
    }

    // epilogue
    #pragma unroll
    for (int mi = 0; mi < 2; mi++) {
        int r0 = m0 + wm0 + mi * 16 + g;
        int r1 = r0 + 8;
        #pragma unroll
        for (int ni = 0; ni < NI; ni++) {
            int n = n0 + wn0 + ni * 8 + 2 * t;
            float b0 = bias[n], b1 = bias[n + 1];
            float v0 = acc[mi][ni][0] + b0;
            float v1 = acc[mi][ni][1] + b1;
            float v2 = acc[mi][ni][2] + b0;
            float v3 = acc[mi][ni][3] + b1;
            if (MODE == 1) {
                v0 = 0.5f * v0 * (1.f + erff(v0 * 0.70710678118654752f));
                v1 = 0.5f * v1 * (1.f + erff(v1 * 0.70710678118654752f));
                v2 = 0.5f * v2 * (1.f + erff(v2 * 0.70710678118654752f));
                v3 = 0.5f * v3 * (1.f + erff(v3 * 0.70710678118654752f));
                float s0, s1, s2, s3;
                uint32_t m0w = packh_big(v0, v1, s0, s1);
                uint32_t m1w = packh_big(v2, v3, s2, s3);
                *(uint32_t*)&C1[(size_t)r0 * Ncols + n] = m0w;
                *(uint32_t*)&C1[(size_t)r1 * Ncols + n] = m1w;
                *(uint32_t*)&C2[(size_t)r0 * Ncols + n] = packh(s0, s1);
                *(uint32_t*)&C2[(size_t)r1 * Ncols + n] = packh(s2, s3);
            } else {
                if (MODE == 2) {
                    v0 += res[(size_t)r0 * Ncols + n];
                    v1 += res[(size_t)r0 * Ncols + n + 1];
                    v2 += res[(size_t)r1 * Ncols + n];
                    v3 += res[(size_t)r1 * Ncols + n + 1];
                }
                *(float2*)&C[(size_t)r0 * Ncols + n] = make_float2(v0, v1);
                *(float2*)&C[(size_t)r1 * Ncols + n] = make_float2(v2, v3);
            }
        }
    }
}

// ---------------- fused patchify + select (one launch) ------------------------
__global__ void k_patchsel(const float* __restrict__ x,
                           const float* __restrict__ attn_mask,
                           const int*   __restrict__ yids,
                           const float* __restrict__ conv_w,
                           const float* __restrict__ conv_b,
                           const float* __restrict__ pex,
                           const float* __restrict__ ytab,
                           const float* __restrict__ noise) {
    if (blockIdx.x >= BB * LL) {
        int b = blockIdx.x - BB * LL;
        __shared__ float ns[LL];
        __shared__ int ids[LL];
        __shared__ unsigned char keep[LL];
        for (int i = threadIdx.x; i < LL; i += blockDim.x) { ns[i] = noise[b * LL + i]; keep[i] = 0; }
        __syncthreads();
        for (int i = threadIdx.x; i < LL; i += blockDim.x) {
            float vi = ns[i];
            int r = 0;
            for (int j = 0; j < LL; j++) {
                float vj = ns[j];
                r += (vj < vi) || (vj == vi && j < i);
            }
            ids[r] = i;
        }
        __syncthreads();
        for (int t = threadIdx.x; t < LEN_KEEP; t += blockDim.x) {
            g_idsk[b * LEN_KEEP + t] = ids[t];
            keep[ids[t]] = 1;
        }
        __syncthreads();
        for (int i = threadIdx.x; i < LL; i += blockDim.x) {
            if (keep[i]) {
                int pos = 0;
                for (int j = 0; j < i; j++) pos += keep[j];
                g_m[b * NTOK + 1 + pos] = attn_mask[b * LL + i];
            }
        }
        if (threadIdx.x == 0) g_m[b * NTOK] = 1.f;
        return;
    }
    int bl = blockIdx.x;
    int b = bl / LL, l = bl % LL;
    int gh = l / GW, gw = l % GW;
    __shared__ float patch[QQ];
    const float* xrow = x + ((size_t)b * HIN + gh) * WIN + gw * QQ;
    for (int i = threadIdx.x; i < QQ; i += blockDim.x) patch[i] = xrow[i];
    __syncthreads();
    float am = attn_mask[b * LL + l];
    int yid = yids[b * LL + l];
    for (int d = threadIdx.x; d < DD; d += blockDim.x) {
        const float* w = conv_w + d * QQ;
        float acc = 0.f;
        #pragma unroll 4
        for (int q = 0; q < QQ; q++) acc += patch[q] * w[q];
        acc += conv_b[d];
        if (d < DH) acc += ytab[yid * DH + d];
        else        acc += am * pex[(gw + 1) * DH + (d - DH)];
        g_hfull[((size_t)b * LL + l) * DD + d] = acc;
    }
}

// ---------------- fused gather + layer-0 LN1 (split fp16) + gmax reset --------
__global__ void k_gather_ln(const float* __restrict__ cls_token,
                            const float* __restrict__ pex,
                            const float* __restrict__ w,
                            const float* __restrict__ bias) {
    int bt = blockIdx.x;
    int b = bt / NTOK, t = bt % NTOK;
    if (bt == 0 && threadIdx.x == 0) g_gmax = 0u;
    __shared__ float row[DD];
    __shared__ float red[256];
    float* outp = g_carry + (size_t)bt * DD;
    if (t == 0) {
        for (int d = threadIdx.x; d < DD; d += 256) {
            float v = cls_token[d] + (d >= DH ? pex[d - DH] : 0.f);
            row[d] = v; outp[d] = v;
        }
    } else {
        int l = g_idsk[b * LEN_KEEP + (t - 1)];
        const float* src = g_hfull + ((size_t)b * LL + l) * DD;
        for (int d = threadIdx.x; d < DD; d += 256) {
            float v = src[d];
            row[d] = v; outp[d] = v;
        }
    }
    __syncthreads();
    float s = 0.f;
    for (int d = threadIdx.x; d < DD; d += 256) s += row[d];
    red[threadIdx.x] = s; __syncthreads();
    for (int o = 128; o > 0; o >>= 1) {
        if (threadIdx.x < o) red[threadIdx.x] += red[threadIdx.x + o];
        __syncthreads();
    }
    float mu = red[0] * (1.f / DD);
    __syncthreads();
    float v = 0.f;
    for (int d = threadIdx.x; d < DD; d += 256) { float u = row[d] - mu; v += u * u; }
    red[threadIdx.x] = v; __syncthreads();
    for (int o = 128; o > 0; o >>= 1) {
        if (threadIdx.x < o) red[threadIdx.x] += red[threadIdx.x + o];
        __syncthreads();
    }
    float rstd = rsqrtf(red[0] * (1.f / DD) + EPS_LN);
    for (int d = threadIdx.x; d < DD; d += 256) {
        float val = (row[d] - mu) * rstd * w[d] + bias[d];
        __half h = __float2half_rn(val);
        g_act1[(size_t)bt * DD + d] = h;
        g_act2[(size_t)bt * DD + d] = __float2half_rn(val - __half2float(h));
    }
}

// ---------------- layernorm (fp32 out, final) ---------------------------------
__global__ void k_ln(const float* __restrict__ in,
                     const float* __restrict__ w,
                     const float* __restrict__ bias,
                     float* __restrict__ out) {
    int r = blockIdx.x;
    const float* p = in + (size_t)r * DD;
    __shared__ float red[256];
    float s = 0.f;
    for (int d = threadIdx.x; d < DD; d += 256) s += p[d];
    red[threadIdx.x] = s; __syncthreads();
    for (int o = 128; o > 0; o >>= 1) {
        if (threadIdx.x < o) red[threadIdx.x] += red[threadIdx.x + o];
        __syncthreads();
    }
    float mu = red[0] * (1.f / DD);
    __syncthreads();
    float v = 0.f;
    for (int d = threadIdx.x; d < DD; d += 256) { float t = p[d] - mu; v += t * t; }
    red[threadIdx.x] = v; __syncthreads();
    for (int o = 128; o > 0; o >>= 1) {
        if (threadIdx.x < o) red[threadIdx.x] += red[threadIdx.x + o];
        __syncthreads();
    }
    float rstd = rsqrtf(red[0] * (1.f / DD) + EPS_LN);
    for (int d = threadIdx.x; d < DD; d += 256)
        out[(size_t)r * DD + d] = (p[d] - mu) * rstd * w[d] + bias[d];
}

// ---------------- layernorm (split fp16 out; also resets g_gmax) --------------
__global__ void k_ln_sp(const float* __restrict__ in,
                        const float* __restrict__ w,
                        const float* __restrict__ bias) {
    int r = blockIdx.x;
    if (r == 0 && threadIdx.x == 0) g_gmax = 0u;
    const float* p = in + (size_t)r * DD;
    __shared__ float red[256];
    float s = 0.f;
    for (int d = threadIdx.x; d < DD; d += 256) s += p[d];
    red[threadIdx.x] = s; __syncthreads();
    for (int o = 128; o > 0; o >>= 1) {
        if (threadIdx.x < o) red[threadIdx.x] += red[threadIdx.x + o];
        __syncthreads();
    }
    float mu = red[0] * (1.f / DD);
    __syncthreads();
    float v = 0.f;
    for (int d = threadIdx.x; d < DD; d += 256) { float t = p[d] - mu; v += t * t; }
    red[threadIdx.x] = v; __syncthreads();
    for (int o = 128; o > 0; o >>= 1) {
        if (threadIdx.x < o) red[threadIdx.x] += red[threadIdx.x + o];
        __syncthreads();
    }
    float rstd = rsqrtf(red[0] * (1.f / DD) + EPS_LN);
    for (int d = threadIdx.x; d < DD; d += 256) {
        float val = (p[d] - mu) * rstd * w[d] + bias[d];
        __half h = __float2half_rn(val);
        g_act1[(size_t)r * DD + d] = h;
        g_act2[(size_t)r * DD + d] = __float2half_rn(val - __half2float(h));
    }
}

// ---------------- attention scores: one block per (b,h), float4 dots ----------
__global__ void __launch_bounds__(256)
k_scores_bh() {
    int bh = blockIdx.x;
    int h = bh % NHD, b = bh / NHD;
    __shared__ float4 Q4[NTOK][17];
    __shared__ float4 K4[NTOK][17];
    __shared__ float msh[NTOK];
    __shared__ float wmax[8];
    int tid = threadIdx.x;
    const float4* qkv4 = (const float4*)g_qkv;
    for (int idx = tid; idx < NTOK * 16; idx += 256) {
        int r = idx >> 4, d4 = idx & 15;
        size_t base = (size_t)(b * NTOK + r) * (3 * DD / 4) + h * 16 + d4;
        Q4[r][d4] = qkv4[base];
        K4[r][d4] = qkv4[base + DD / 4];
    }
    for (int i = tid; i < NTOK; i += 256) msh[i] = g_m[b * NTOK + i];
    __syncthreads();
    int w = tid >> 5, lane = tid & 31;
    float lmax = -3.4e38f;
    for (int n = w; n < NTOK; n += 8) {
        float mn = msh[n];
        float* outrow = &g_att[((size_t)bh * NTOK + n) * NTOK];
        for (int m = lane; m < NTOK; m += 32) {
            float dot = 0.f;
            #pragma unroll
            for (int d4 = 0; d4 < 16; d4++) {
                float4 q = Q4[n][d4];
                float4 k = K4[m][d4];
                dot = fmaf(q.x, k.x, dot);
                dot = fmaf(q.y, k.y, dot);
                dot = fmaf(q.z, k.z, dot);
                dot = fmaf(q.w, k.w, dot);
            }
            float logit = dot * SCALE;
            if (mn * msh[m] == 0.f) logit = -INFINITY;
            else lmax = fmaxf(lmax, logit);
            outrow[m] = logit;
        }
    }
    #pragma unroll
    for (int o = 16; o > 0; o >>= 1)
        lmax = fmaxf(lmax, __shfl_xor_sync(0xffffffffu, lmax, o));
    if (lane == 0) wmax[w] = lmax;
    __syncthreads();
    if (tid == 0) {
        float bm = wmax[0];
        #pragma unroll
        for (int i = 1; i < 8; i++) bm = fmaxf(bm, wmax[i]);
        if (bm > -3.3e38f) atomicMax(&g_gmax, fenc(bm));
    }
}

// ---------------- softmax + AV (float4 V, parity m-split) -> split fp16 -------
__global__ void __launch_bounds__(256)
k_softmax_bh() {
    int bh = blockIdx.x;
    int h = bh % NHD, b = bh / NHD;
    __shared__ float4 V4[NTOK][17];
    __shared__ float Psh[NTOK][77];
    __shared__ float rsum[NTOK];
    int tid = threadIdx.x;
    const float4* qkv4 = (const float4*)g_qkv;
    for (int idx = tid; idx < NTOK * 16; idx += 256) {
        int r = idx >> 4, d4 = idx & 15;
        V4[r][d4] = qkv4[(size_t)(b * NTOK + r) * (3 * DD / 4) + 2 * DD / 4 + h * 16 + d4];
    }
    __syncthreads();
    int w = tid >> 5, lane = tid & 31;
    float gmx = fdec(g_gmax);
    for (int n = w; n < NTOK; n += 8) {
        const float* arow = &g_att[((size_t)bh * NTOK + n) * NTOK];
        float s = 0.f;
        for (int m = lane; m < NTOK; m += 32) {
            float e = expf(arow[m] - gmx);
            Psh[n][m] = e;
            s += e;
        }
        #pragma unroll
        for (int o = 16; o > 0; o >>= 1) s += __shfl_xor_sync(0xffffffffu, s, o);
        if (lane == 0) rsum[n] = s;
    }
    __syncthreads();
    // AV: lanes 0..15 cover d4 0..15 with m even; lanes 16..31 same d4, m odd
    int d4 = lane & 15, par = lane >> 4;
    for (int n = w; n < NTOK; n += 8) {
        float inv = 1.f / (rsum[n] + 1e-9f);
        float4 acc = make_float4(0.f, 0.f, 0.f, 0.f);
        for (int m = par; m < NTOK; m += 2) {
            float p = Psh[n][m];
            float4 v = V4[m][d4];
            acc.x = fmaf(p, v.x, acc.x);
            acc.y = fmaf(p, v.y, acc.y);
            acc.z = fmaf(p, v.z, acc.z);
            acc.w = fmaf(p, v.w, acc.w);
        }
        acc.x += __shfl_down_sync(0xffffffffu, acc.x, 16);
        acc.y += __shfl_down_sync(0xffffffffu, acc.y, 16);
        acc.z += __shfl_down_sync(0xffffffffu, acc.z, 16);
        acc.w += __shfl_down_sync(0xffffffffu, acc.w, 16);
        if (par == 0) {
            size_t o2 = (size_t)(b * NTOK + n) * DD + h * HD + d4 * 4;
            float vals[4] = {acc.x * inv, acc.y * inv, acc.z * inv, acc.w * inv};
            uint32_t m1, m2, s1w, s2w;
            {
                float r0, r1, r2, r3;
                m1 = packh_big(vals[0], vals[1], r0, r1);
                m2 = packh_big(vals[2], vals[3], r2, r3);
                s1w = packh(r0, r1);
                s2w = packh(r2, r3);
            }
            *(uint2*)&g_act1[o2] = make_uint2(m1, m2);
            *(uint2*)&g_act2[o2] = make_uint2(s1w, s2w);
        }
    }
}

// ---------------- launch -----------------------------------------------------
extern "C" void kernel_launch(void* const* d_in, const int* in_sizes, int n_in,
                              void* d_out, int out_size) {
    const float* x         = (const float*)d_in[0];
    const float* attn_mask = (const float*)d_in[1];
    const int*   yids      = (const int*)  d_in[2];
    const float* noise     = (const float*)d_in[3];
    const float* conv_w    = (const float*)d_in[4];
    const float* conv_b    = (const float*)d_in[5];
    const float* pex       = (const float*)d_in[6];
    const float* ytab      = (const float*)d_in[7];
    const float* cls       = (const float*)d_in[8];
    const float* qkv_w     = (const float*)d_in[9];
    const float* qkv_b     = (const float*)d_in[10];
    const float* proj_w    = (const float*)d_in[11];
    const float* proj_b    = (const float*)d_in[12];
    const float* ln1_w     = (const float*)d_in[13];
    const float* ln1_b     = (const float*)d_in[14];
    const float* ln2_w     = (const float*)d_in[15];
    const float* ln2_b     = (const float*)d_in[16];
    const float* fc1_w     = (const float*)d_in[17];
    const float* fc1_b     = (const float*)d_in[18];
    const float* fc2_w     = (const float*)d_in[19];
    const float* fc2_b     = (const float*)d_in[20];
    const float* norm_w    = (const float*)d_in[21];
    const float* norm_b    = (const float*)d_in[22];
    float* out = (float*)d_out;

    float *carry, *qkv;
    __half *act1, *act2, *hid1, *hid2, *wq, *wp, *w1, *w2;
    cudaGetSymbolAddress((void**)&carry, g_carry);
    cudaGetSymbolAddress((void**)&qkv,   g_qkv);
    cudaGetSymbolAddress((void**)&act1,  g_act1);
    cudaGetSymbolAddress((void**)&act2,  g_act2);
    cudaGetSymbolAddress((void**)&hid1,  g_hid1);
    cudaGetSymbolAddress((void**)&hid2,  g_hid2);
    cudaGetSymbolAddress((void**)&wq,    g_wq);
    cudaGetSymbolAddress((void**)&wp,    g_wp);
    cudaGetSymbolAddress((void**)&w1,    g_w1);
    cudaGetSymbolAddress((void**)&w2,    g_w2);

    const int SM192 = 3 * (256 + 192) * 80;  // 107520 -> 1 CTA/SM (120 CTAs)
    const int SM128 = 3 * (256 + 128) * 80;  // 92160  -> 2 CTAs/SM
    const int SM64  = 4 * (256 + 64)  * 80;  // 102400 -> 2 CTAs/SM
    cudaFuncSetAttribute(k_gemm_f16<192, 0, 3, 1>, cudaFuncAttributeMaxDynamicSharedMemorySize, SM192);
    cudaFuncSetAttribute(k_gemm_f16<128, 1, 3, 2>, cudaFuncAttributeMaxDynamicSharedMemorySize, SM128);
    cudaFuncSetAttribute(k_gemm_f16<64, 2, 4, 2>,  cudaFuncAttributeMaxDynamicSharedMemorySize, SM64);

    const int MT = M_PAD / 128;  // 10

    k_split_all<<<4096, 256>>>((const float4*)qkv_w, (const float4*)proj_w,
                               (const float4*)fc1_w, (const float4*)fc2_w);
    k_patchsel<<<BB * LL + BB, 256>>>(x, attn_mask, yids, conv_w, conv_b, pex, ytab, noise);
    k_gather_ln<<<MROWS, 256>>>(cls, pex, ln1_w, ln1_b);

    for (int l = 0; l < DEPTH; l++) {
        const float* qb  = qkv_b  + (size_t)l * 3 * DD;
        const float* pb  = proj_b + (size_t)l * DD;
        const float* l1w = ln1_w + l * DD; const float* l1b = ln1_b + l * DD;
        const float* l2w = ln2_w + l * DD; const float* l2b = ln2_b + l * DD;
        const float* f1b = fc1_b + (size_t)l * MLPD;
        const float* f2b = fc2_b + (size_t)l * DD;
        __half* lwq = wq + (size_t)l * 3 * DD * DD;
        __half* lwp = wp + (size_t)l * DD * DD;
        __half* lw1 = w1 + (size_t)l * MLPD * DD;
        __half* lw2 = w2 + (size_t)l * DD * MLPD;

        if (l > 0) k_ln_sp<<<MROWS, 256>>>(carry, l1w, l1b);
        k_gemm_f16<192, 0, 3, 1><<<dim3(3 * DD / 192, MT), 256, SM192>>>(
            act1, act2, lwq, qb, nullptr, qkv, nullptr, nullptr, 3 * DD, DD);
        k_scores_bh<<<BB * NHD, 256>>>();
        k_softmax_bh<<<BB * NHD, 256>>>();
        k_gemm_f16<64, 2, 4, 2><<<dim3(DD / 64, MT), 256, SM64>>>(
            act1, act2, lwp, pb, carry, carry, nullptr, nullptr, DD, DD);
        k_ln_sp<<<MROWS, 256>>>(carry, l2w, l2b);
        k_gemm_f16<128, 1, 3, 2><<<dim3(MLPD / 128, MT), 256, SM128>>>(
            act1, act2, lw1, f1b, nullptr, nullptr, hid1, hid2, MLPD, DD);
        k_gemm_f16<64, 2, 4, 2><<<dim3(DD / 64, MT), 256, SM64>>>(
            hid1, hid2, lw2, f2b, carry, carry, nullptr, nullptr, DD, MLPD);
    }

    k_ln<<<MROWS, 256>>>(carry, norm_w, norm_b, out);
}

// round 15
// speedup vs baseline: 1.1501x; 1.0322x over previous
#include <cuda_runtime.h>
#include <cuda_fp16.h>
#include <math.h>
#include <cstdint>

#define BB   16
#define HIN  12
#define WIN  2500
#define QQ   100
#define GW   25
#define LL   300
#define LEN_KEEP 75
#define NTOK 76
#define DD   768
#define DH   384
#define NHD  12
#define HD   64
#define DEPTH 12
#define MLPD 3072
#define SCALE 0.125f
#define EPS_LN 1e-5f
#define MROWS (BB * NTOK)     // 1216
#define M_PAD 1280            // 10 tiles of 128

#define QWN  (DEPTH * 3 * DD * DD)
#define PWN  (DEPTH * DD * DD)
#define F1N  (DEPTH * MLPD * DD)
#define F2N  (DEPTH * DD * MLPD)

// ---------------- scratch (device globals; no allocation allowed) -----------
__device__ float g_hfull[BB * LL * DD];
__device__ float g_carry[M_PAD * DD];
__device__ float g_qkv[M_PAD * 3 * DD];
__device__ int   g_idsk[BB * LEN_KEEP];
__device__ float g_m[BB * NTOK];
__device__ unsigned g_gmax;
__device__ unsigned g_cnt;

// split activations (fp16 main + fp16 residual)
__device__ __half g_act1[M_PAD * DD],   g_act2[M_PAD * DD];
__device__ __half g_hid1[M_PAD * MLPD], g_hid2[M_PAD * MLPD];
// fp16-rounded weights (single term)
__device__ __half g_wq[QWN];
__device__ __half g_wp[PWN];
__device__ __half g_w1[F1N];
__device__ __half g_w2[F2N];

// monotone float<->uint encoding for atomicMax on floats
__device__ __forceinline__ unsigned fenc(float f) {
    unsigned u = __float_as_uint(f);
    return (u & 0x80000000u) ? ~u : (u | 0x80000000u);
}
__device__ __forceinline__ float fdec(unsigned u) {
    return (u & 0x80000000u) ? __uint_as_float(u & 0x7fffffffu) : __uint_as_float(~u);
}

// ---------------- asm helpers -------------------------------------------------
#define CP_ASYNC16(dst, src) \
    asm volatile("cp.async.cg.shared.global [%0], [%1], 16;" :: "r"(dst), "l"(src))
#define CP_COMMIT() asm volatile("cp.async.commit_group;" ::: "memory")
#define LDSM4(r0, r1, r2, r3, addr)                                          \
    asm volatile("ldmatrix.sync.aligned.m8n8.x4.shared.b16 {%0,%1,%2,%3}, [%4];" \
        : "=r"(r0), "=r"(r1), "=r"(r2), "=r"(r3) : "r"(addr))

__device__ __forceinline__ void mma_fp16(float* d, const uint32_t* a,
                                         uint32_t b0, uint32_t b1) {
    asm volatile(
        "mma.sync.aligned.m16n8k16.row.col.f32.f16.f16.f32 "
        "{%0,%1,%2,%3}, {%4,%5,%6,%7}, {%8,%9}, {%0,%1,%2,%3};"
        : "+f"(d[0]), "+f"(d[1]), "+f"(d[2]), "+f"(d[3])
        : "r"(a[0]), "r"(a[1]), "r"(a[2]), "r"(a[3]), "r"(b0), "r"(b1));
}

__device__ __forceinline__ uint32_t packh(float v0, float v1) {
    __half2 h = __floats2half2_rn(v0, v1);
    return *(uint32_t*)&h;
}
__device__ __forceinline__ uint32_t packh_big(float v0, float v1, float& r0, float& r1) {
    __half h0 = __float2half_rn(v0);
    __half h1 = __float2half_rn(v1);
    r0 = v0 - __half2float(h0);
    r1 = v1 - __half2float(h1);
    __half2 h = __halves2half2(h0, h1);
    return *(uint32_t*)&h;
}

// ---------------- merged weight round kernel (single launch) ------------------
__global__ void k_split_all(const float4* __restrict__ qw, const float4* __restrict__ pw,
                            const float4* __restrict__ f1, const float4* __restrict__ f2) {
    const int q4 = QWN / 4, p4 = PWN / 4, a4 = F1N / 4, b4 = F2N / 4;
    const int total = q4 + p4 + a4 + b4;
    for (int i = blockIdx.x * blockDim.x + threadIdx.x; i < total;
         i += gridDim.x * blockDim.x) {
        const float4* src;
        __half* dst;
        int j = i;
        if (j < q4)               { src = qw; dst = g_wq; }
        else if ((j -= q4) < p4)  { src = pw; dst = g_wp; }
        else if ((j -= p4) < a4)  { src = f1; dst = g_w1; }
        else { j -= a4;             src = f2; dst = g_w2; }
        float4 v = src[j];
        *(uint2*)&dst[(size_t)j * 4] = make_uint2(packh(v.x, v.y), packh(v.z, v.w));
    }
}

// ---------------- fp16 two-term pipelined GEMM --------------------------------
template <int BN, int MODE, int NST, int MAXCTA>
__global__ void __launch_bounds__(256, MAXCTA)
k_gemm_f16(const __half* __restrict__ A1_g, const __half* __restrict__ A2_g,
           const __half* __restrict__ W_g,
           const float* __restrict__ bias, const float* __restrict__ res,
           float* __restrict__ C, __half* __restrict__ C1,
           __half* __restrict__ C2, int Ncols, int K) {
    extern __shared__ char sh[];
    const uint32_t STAGE = (256 + BN) * 80;
    const uint32_t AOFF = 128 * 80;
    uint32_t sbase = (uint32_t)__cvta_generic_to_shared(sh);

    const int tid = threadIdx.x;
    const int wid = tid >> 5, lane = tid & 31;
    const int g = lane >> 2, t = lane & 3;
    const int lrow = lane & 7, seg = lane >> 3;
    const int warp_m = wid & 3, warp_n = wid >> 2;
    const int wm0 = warp_m * 32;
    const int wn0 = warp_n * (BN / 2);
    const int m0 = blockIdx.y * 128, n0 = blockIdx.x * BN;
    const int NI = BN / 16;
    const int NCH = (256 + BN) * 4;
    const int nC = K >> 5;

    float acc[2][NI][4];
    #pragma unroll
    for (int mi = 0; mi < 2; mi++)
        #pragma unroll
        for (int ni = 0; ni < NI; ni++)
            #pragma unroll
            for (int j = 0; j < 4; j++) acc[mi][ni][j] = 0.f;

    auto load = [&](int c) {
        int k0 = c << 5;
        uint32_t base = sbase + (uint32_t)(c % NST) * STAGE;
        #pragma unroll
        for (int i = tid; i < NCH; i += 256) {
            const __half* gsrc;
            uint32_t dst;
            if (i < 512) {
                int row = i >> 2, j = i & 3;
                gsrc = A1_g + (size_t)(m0 + row) * K + k0 + j * 8;
                dst = base + row * 80 + j * 16;
            } else if (i < 1024) {
                int i2 = i - 512;
                int row = i2 >> 2, j = i2 & 3;
                gsrc = A2_g + (size_t)(m0 + row) * K + k0 + j * 8;
                dst = base + AOFF + row * 80 + j * 16;
            } else {
                int i2 = i - 1024;
                int row = i2 >> 2, j = i2 & 3;
                gsrc = W_g + (size_t)(n0 + row) * K + k0 + j * 8;
                dst = base + 2 * AOFF + row * 80 + j * 16;
            }
            CP_ASYNC16(dst, gsrc);
        }
        CP_COMMIT();
    };

    #pragma unroll
    for (int s = 0; s < NST - 1; s++) load(s);

    for (int c = 0; c < nC; c++) {
        if (c + NST - 1 < nC) {
            asm volatile("cp.async.wait_group %0;" :: "n"(NST - 2));
        } else {
            asm volatile("cp.async.wait_group 0;" ::: "memory");
        }
        __syncthreads();
        if (c + NST - 1 < nC) load(c + NST - 1);

        uint32_t base = sbase + (uint32_t)(c % NST) * STAGE;
        uint32_t a1B = base, a2B = base + AOFF;
        uint32_t wB = base + 2 * AOFF;

        #pragma unroll
        for (int ks = 0; ks < 2; ks++) {
            uint32_t x[2][4], y[2][4];
            #pragma unroll
            for (int mi = 0; mi < 2; mi++) {
                uint32_t off = (uint32_t)((wm0 + mi * 16 + (seg & 1) * 8 + lrow) * 80
                                          + ks * 32 + (seg >> 1) * 16);
                LDSM4(x[mi][0], x[mi][1], x[mi][2], x[mi][3], a1B + off);
                LDSM4(y[mi][0], y[mi][1], y[mi][2], y[mi][3], a2B + off);
            }
            #pragma unroll
            for (int np = 0; np < NI / 2; np++) {
                uint32_t off = (uint32_t)((wn0 + np * 16 + (seg >> 1) * 8 + lrow) * 80
                                          + ks * 32 + (seg & 1) * 16);
                uint32_t w0, w1, w2, w3;
                LDSM4(w0, w1, w2, w3, wB + off);
                int n1 = 2 * np, n2 = 2 * np + 1;
                #pragma unroll
                for (int mi = 0; mi < 2; mi++) mma_fp16(acc[mi][n1], x[mi], w0, w1);
                #pragma unroll
                for (int mi = 0; mi < 2; mi++) mma_fp16(acc[mi][n2], x[mi], w2, w3);
                #pragma unroll
                for (int mi = 0; mi < 2; mi++) mma_fp16(acc[mi][n1], y[mi], w0, w1);
                #pragma unroll
                for (int mi = 0; mi < 2; mi++) mma_fp16(acc[mi][n2], y[mi], w2, w3);
            }
        }
    }

    // epilogue
    #pragma unroll
    for (int mi = 0; mi < 2; mi++) {
        int r0 = m0 + wm0 + mi * 16 + g;
        int r1 = r0 + 8;
        #pragma unroll
        for (int ni = 0; ni < NI; ni++) {
            int n = n0 + wn0 + ni * 8 + 2 * t;
            float b0 = bias[n], b1 = bias[n + 1];
            float v0 = acc[mi][ni][0] + b0;
            float v1 = acc[mi][ni][1] + b1;
            float v2 = acc[mi][ni][2] + b0;
            float v3 = acc[mi][ni][3] + b1;
            if (MODE == 1) {
                v0 = 0.5f * v0 * (1.f + erff(v0 * 0.70710678118654752f));
                v1 = 0.5f * v1 * (1.f + erff(v1 * 0.70710678118654752f));
                v2 = 0.5f * v2 * (1.f + erff(v2 * 0.70710678118654752f));
                v3 = 0.5f * v3 * (1.f + erff(v3 * 0.70710678118654752f));
                float s0, s1, s2, s3;
                uint32_t m0w = packh_big(v0, v1, s0, s1);
                uint32_t m1w = packh_big(v2, v3, s2, s3);
                *(uint32_t*)&C1[(size_t)r0 * Ncols + n] = m0w;
                *(uint32_t*)&C1[(size_t)r1 * Ncols + n] = m1w;
                *(uint32_t*)&C2[(size_t)r0 * Ncols + n] = packh(s0, s1);
                *(uint32_t*)&C2[(size_t)r1 * Ncols + n] = packh(s2, s3);
            } else {
                if (MODE == 2) {
                    v0 += res[(size_t)r0 * Ncols + n];
                    v1 += res[(size_t)r0 * Ncols + n + 1];
                    v2 += res[(size_t)r1 * Ncols + n];
                    v3 += res[(size_t)r1 * Ncols + n + 1];
                }
                *(float2*)&C[(size_t)r0 * Ncols + n] = make_float2(v0, v1);
                *(float2*)&C[(size_t)r1 * Ncols + n] = make_float2(v2, v3);
            }
        }
    }
}

// ---------------- fused patchify + select (one launch) ------------------------
__global__ void k_patchsel(const float* __restrict__ x,
                           const float* __restrict__ attn_mask,
                           const int*   __restrict__ yids,
                           const float* __restrict__ conv_w,
                           const float* __restrict__ conv_b,
                           const float* __restrict__ pex,
                           const float* __restrict__ ytab,
                           const float* __restrict__ noise) {
    if (blockIdx.x >= BB * LL) {
        int b = blockIdx.x - BB * LL;
        __shared__ float ns[LL];
        __shared__ int ids[LL];
        __shared__ unsigned char keep[LL];
        for (int i = threadIdx.x; i < LL; i += blockDim.x) { ns[i] = noise[b * LL + i]; keep[i] = 0; }
        __syncthreads();
        for (int i = threadIdx.x; i < LL; i += blockDim.x) {
            float vi = ns[i];
            int r = 0;
            for (int j = 0; j < LL; j++) {
                float vj = ns[j];
                r += (vj < vi) || (vj == vi && j < i);
            }
            ids[r] = i;
        }
        __syncthreads();
        for (int t = threadIdx.x; t < LEN_KEEP; t += blockDim.x) {
            g_idsk[b * LEN_KEEP + t] = ids[t];
            keep[ids[t]] = 1;
        }
        __syncthreads();
        for (int i = threadIdx.x; i < LL; i += blockDim.x) {
            if (keep[i]) {
                int pos = 0;
                for (int j = 0; j < i; j++) pos += keep[j];
                g_m[b * NTOK + 1 + pos] = attn_mask[b * LL + i];
            }
        }
        if (threadIdx.x == 0) g_m[b * NTOK] = 1.f;
        return;
    }
    int bl = blockIdx.x;
    int b = bl / LL, l = bl % LL;
    int gh = l / GW, gw = l % GW;
    __shared__ float patch[QQ];
    const float* xrow = x + ((size_t)b * HIN + gh) * WIN + gw * QQ;
    for (int i = threadIdx.x; i < QQ; i += blockDim.x) patch[i] = xrow[i];
    __syncthreads();
    float am = attn_mask[b * LL + l];
    int yid = yids[b * LL + l];
    for (int d = threadIdx.x; d < DD; d += blockDim.x) {
        const float* w = conv_w + d * QQ;
        float acc = 0.f;
        #pragma unroll 4
        for (int q = 0; q < QQ; q++) acc += patch[q] * w[q];
        acc += conv_b[d];
        if (d < DH) acc += ytab[yid * DH + d];
        else        acc += am * pex[(gw + 1) * DH + (d - DH)];
        g_hfull[((size_t)b * LL + l) * DD + d] = acc;
    }
}

// ---------------- fused gather + layer-0 LN1 + gmax/cnt reset -----------------
__global__ void k_gather_ln(const float* __restrict__ cls_token,
                            const float* __restrict__ pex,
                            const float* __restrict__ w,
                            const float* __restrict__ bias) {
    int bt = blockIdx.x;
    int b = bt / NTOK, t = bt % NTOK;
    if (bt == 0 && threadIdx.x == 0) { g_gmax = 0u; g_cnt = 0u; }
    __shared__ float row[DD];
    __shared__ float red[256];
    float* outp = g_carry + (size_t)bt * DD;
    if (t == 0) {
        for (int d = threadIdx.x; d < DD; d += 256) {
            float v = cls_token[d] + (d >= DH ? pex[d - DH] : 0.f);
            row[d] = v; outp[d] = v;
        }
    } else {
        int l = g_idsk[b * LEN_KEEP + (t - 1)];
        const float* src = g_hfull + ((size_t)b * LL + l) * DD;
        for (int d = threadIdx.x; d < DD; d += 256) {
            float v = src[d];
            row[d] = v; outp[d] = v;
        }
    }
    __syncthreads();
    float s = 0.f;
    for (int d = threadIdx.x; d < DD; d += 256) s += row[d];
    red[threadIdx.x] = s; __syncthreads();
    for (int o = 128; o > 0; o >>= 1) {
        if (threadIdx.x < o) red[threadIdx.x] += red[threadIdx.x + o];
        __syncthreads();
    }
    float mu = red[0] * (1.f / DD);
    __syncthreads();
    float v = 0.f;
    for (int d = threadIdx.x; d < DD; d += 256) { float u = row[d] - mu; v += u * u; }
    red[threadIdx.x] = v; __syncthreads();
    for (int o = 128; o > 0; o >>= 1) {
        if (threadIdx.x < o) red[threadIdx.x] += red[threadIdx.x + o];
        __syncthreads();
    }
    float rstd = rsqrtf(red[0] * (1.f / DD) + EPS_LN);
    for (int d = threadIdx.x; d < DD; d += 256) {
        float val = (row[d] - mu) * rstd * w[d] + bias[d];
        __half h = __float2half_rn(val);
        g_act1[(size_t)bt * DD + d] = h;
        g_act2[(size_t)bt * DD + d] = __float2half_rn(val - __half2float(h));
    }
}

// ---------------- warp-per-row layernorm -> split fp16 (+ gmax reset) ---------
__global__ void __launch_bounds__(256)
k_ln_sp_w(const float* __restrict__ in, const float* __restrict__ w,
          const float* __restrict__ bias) {
    if (blockIdx.x == 0 && threadIdx.x == 0) g_gmax = 0u;
    int row = blockIdx.x * 8 + (threadIdx.x >> 5);
    int lane = threadIdx.x & 31;
    const float4* p = (const float4*)(in + (size_t)row * DD);
    float4 v[6];
    float s = 0.f;
    #pragma unroll
    for (int k = 0; k < 6; k++) {
        v[k] = p[lane + k * 32];
        s += v[k].x + v[k].y + v[k].z + v[k].w;
    }
    #pragma unroll
    for (int o = 16; o > 0; o >>= 1) s += __shfl_xor_sync(0xffffffffu, s, o);
    float mu = s * (1.f / DD);
    float var = 0.f;
    #pragma unroll
    for (int k = 0; k < 6; k++) {
        float a = v[k].x - mu, b2 = v[k].y - mu, c = v[k].z - mu, d = v[k].w - mu;
        var += a * a + b2 * b2 + c * c + d * d;
    }
    #pragma unroll
    for (int o = 16; o > 0; o >>= 1) var += __shfl_xor_sync(0xffffffffu, var, o);
    float rstd = rsqrtf(var * (1.f / DD) + EPS_LN);
    const float4* w4 = (const float4*)w;
    const float4* b4 = (const float4*)bias;
    #pragma unroll
    for (int k = 0; k < 6; k++) {
        int idx = lane + k * 32;
        float4 ww = w4[idx], bb = b4[idx];
        float x0 = (v[k].x - mu) * rstd * ww.x + bb.x;
        float x1 = (v[k].y - mu) * rstd * ww.y + bb.y;
        float x2 = (v[k].z - mu) * rstd * ww.z + bb.z;
        float x3 = (v[k].w - mu) * rstd * ww.w + bb.w;
        float r0, r1, r2, r3;
        uint32_t m1 = packh_big(x0, x1, r0, r1);
        uint32_t m2 = packh_big(x2, x3, r2, r3);
        size_t o2 = (size_t)row * DD + idx * 4;
        *(uint2*)&g_act1[o2] = make_uint2(m1, m2);
        *(uint2*)&g_act2[o2] = make_uint2(packh(r0, r1), packh(r2, r3));
    }
}

// ---------------- warp-per-row layernorm (fp32 out, final) --------------------
__global__ void __launch_bounds__(256)
k_ln_w(const float* __restrict__ in, const float* __restrict__ w,
       const float* __restrict__ bias, float* __restrict__ out) {
    int row = blockIdx.x * 8 + (threadIdx.x >> 5);
    int lane = threadIdx.x & 31;
    const float4* p = (const float4*)(in + (size_t)row * DD);
    float4 v[6];
    float s = 0.f;
    #pragma unroll
    for (int k = 0; k < 6; k++) {
        v[k] = p[lane + k * 32];
        s += v[k].x + v[k].y + v[k].z + v[k].w;
    }
    #pragma unroll
    for (int o = 16; o > 0; o >>= 1) s += __shfl_xor_sync(0xffffffffu, s, o);
    float mu = s * (1.f / DD);
    float var = 0.f;
    #pragma unroll
    for (int k = 0; k < 6; k++) {
        float a = v[k].x - mu, b2 = v[k].y - mu, c = v[k].z - mu, d = v[k].w - mu;
        var += a * a + b2 * b2 + c * c + d * d;
    }
    #pragma unroll
    for (int o = 16; o > 0; o >>= 1) var += __shfl_xor_sync(0xffffffffu, var, o);
    float rstd = rsqrtf(var * (1.f / DD) + EPS_LN);
    const float4* w4 = (const float4*)w;
    const float4* b4 = (const float4*)bias;
    float4* o4 = (float4*)(out + (size_t)row * DD);
    #pragma unroll
    for (int k = 0; k < 6; k++) {
        int idx = lane + k * 32;
        float4 ww = w4[idx], bb = b4[idx];
        float4 r;
        r.x = (v[k].x - mu) * rstd * ww.x + bb.x;
        r.y = (v[k].y - mu) * rstd * ww.y + bb.y;
        r.z = (v[k].z - mu) * rstd * ww.z + bb.z;
        r.w = (v[k].w - mu) * rstd * ww.w + bb.w;
        o4[idx] = r;
    }
}

// ---------------- fused attention: scores + global max (grid barrier) + AV ----
__global__ void __launch_bounds__(256)
k_attn(int layer) {
    int bh = blockIdx.x;
    int h = bh % NHD, b = bh / NHD;
    __shared__ float4 Q4[NTOK][17];   // reused for V after scores
    __shared__ float4 K4[NTOK][17];
    __shared__ float Psh[NTOK][77];
    __shared__ float msh[NTOK];
    __shared__ float wred[8];
    __shared__ float rsum[NTOK];
    __shared__ float sh_gmx;
    int tid = threadIdx.x;
    const float4* qkv4 = (const float4*)g_qkv;
    for (int idx = tid; idx < NTOK * 16; idx += 256) {
        int r = idx >> 4, d4 = idx & 15;
        size_t base = (size_t)(b * NTOK + r) * (3 * DD / 4) + h * 16 + d4;
        Q4[r][d4] = qkv4[base];
        K4[r][d4] = qkv4[base + DD / 4];
    }
    for (int i = tid; i < NTOK; i += 256) msh[i] = g_m[b * NTOK + i];
    __syncthreads();
    int w = tid >> 5, lane = tid & 31;
    float lmax = -3.4e38f;
    for (int n = w; n < NTOK; n += 8) {
        float mn = msh[n];
        for (int m = lane; m < NTOK; m += 32) {
            float dot = 0.f;
            #pragma unroll
            for (int d4 = 0; d4 < 16; d4++) {
                float4 q = Q4[n][d4];
                float4 k = K4[m][d4];
                dot = fmaf(q.x, k.x, dot);
                dot = fmaf(q.y, k.y, dot);
                dot = fmaf(q.z, k.z, dot);
                dot = fmaf(q.w, k.w, dot);
            }
            float logit = dot * SCALE;
            if (mn * msh[m] == 0.f) logit = -INFINITY;
            else lmax = fmaxf(lmax, logit);
            Psh[n][m] = logit;
        }
    }
    #pragma unroll
    for (int o = 16; o > 0; o >>= 1)
        lmax = fmaxf(lmax, __shfl_xor_sync(0xffffffffu, lmax, o));
    if (lane == 0) wred[w] = lmax;
    __syncthreads();
    if (tid == 0) {
        float bm = wred[0];
        #pragma unroll
        for (int i = 1; i < 8; i++) bm = fmaxf(bm, wred[i]);
        if (bm > -3.3e38f) atomicMax(&g_gmax, fenc(bm));
        __threadfence();
        atomicAdd(&g_cnt, 1u);
    }
    __syncthreads();   // scores done: safe to overwrite Q4 with V
    for (int idx = tid; idx < NTOK * 16; idx += 256) {
        int r = idx >> 4, d4 = idx & 15;
        Q4[r][d4] = qkv4[(size_t)(b * NTOK + r) * (3 * DD / 4) + 2 * DD / 4 + h * 16 + d4];
    }
    if (tid == 0) {
        unsigned target = 192u * (unsigned)(layer + 1);
        while (atomicAdd(&g_cnt, 0u) < target) { }
        sh_gmx = fdec(atomicAdd(&g_gmax, 0u));
    }
    __syncthreads();
    float gmx = sh_gmx;
    for (int n = w; n < NTOK; n += 8) {
        float s = 0.f;
        for (int m = lane; m < NTOK; m += 32) {
            float e = expf(Psh[n][m] - gmx);
            Psh[n][m] = e;
            s += e;
        }
        #pragma unroll
        for (int o = 16; o > 0; o >>= 1) s += __shfl_xor_sync(0xffffffffu, s, o);
        if (lane == 0) rsum[n] = s;
    }
    __syncthreads();
    int d4 = lane & 15, par = lane >> 4;
    for (int n = w; n < NTOK; n += 8) {
        float inv = 1.f / (rsum[n] + 1e-9f);
        float4 acc = make_float4(0.f, 0.f, 0.f, 0.f);
        for (int m = par; m < NTOK; m += 2) {
            float p = Psh[n][m];
            float4 v = Q4[m][d4];
            acc.x = fmaf(p, v.x, acc.x);
            acc.y = fmaf(p, v.y, acc.y);
            acc.z = fmaf(p, v.z, acc.z);
            acc.w = fmaf(p, v.w, acc.w);
        }
        acc.x += __shfl_down_sync(0xffffffffu, acc.x, 16);
        acc.y += __shfl_down_sync(0xffffffffu, acc.y, 16);
        acc.z += __shfl_down_sync(0xffffffffu, acc.z, 16);
        acc.w += __shfl_down_sync(0xffffffffu, acc.w, 16);
        if (par == 0) {
            size_t o2 = (size_t)(b * NTOK + n) * DD + h * HD + d4 * 4;
            float vals[4] = {acc.x * inv, acc.y * inv, acc.z * inv, acc.w * inv};
            float r0, r1, r2, r3;
            uint32_t m1 = packh_big(vals[0], vals[1], r0, r1);
            uint32_t m2 = packh_big(vals[2], vals[3], r2, r3);
            *(uint2*)&g_act1[o2] = make_uint2(m1, m2);
            *(uint2*)&g_act2[o2] = make_uint2(packh(r0, r1), packh(r2, r3));
        }
    }
}

// ---------------- launch -----------------------------------------------------
extern "C" void kernel_launch(void* const* d_in, const int* in_sizes, int n_in,
                              void* d_out, int out_size) {
    const float* x         = (const float*)d_in[0];
    const float* attn_mask = (const float*)d_in[1];
    const int*   yids      = (const int*)  d_in[2];
    const float* noise     = (const float*)d_in[3];
    const float* conv_w    = (const float*)d_in[4];
    const float* conv_b    = (const float*)d_in[5];
    const float* pex       = (const float*)d_in[6];
    const float* ytab      = (const float*)d_in[7];
    const float* cls       = (const float*)d_in[8];
    const float* qkv_w     = (const float*)d_in[9];
    const float* qkv_b     = (const float*)d_in[10];
    const float* proj_w    = (const float*)d_in[11];
    const float* proj_b    = (const float*)d_in[12];
    const float* ln1_w     = (const float*)d_in[13];
    const float* ln1_b     = (const float*)d_in[14];
    const float* ln2_w     = (const float*)d_in[15];
    const float* ln2_b     = (const float*)d_in[16];
    const float* fc1_w     = (const float*)d_in[17];
    const float* fc1_b     = (const float*)d_in[18];
    const float* fc2_w     = (const float*)d_in[19];
    const float* fc2_b     = (const float*)d_in[20];
    const float* norm_w    = (const float*)d_in[21];
    const float* norm_b    = (const float*)d_in[22];
    float* out = (float*)d_out;

    float *carry, *qkv;
    __half *act1, *act2, *hid1, *hid2, *wq, *wp, *w1, *w2;
    cudaGetSymbolAddress((void**)&carry, g_carry);
    cudaGetSymbolAddress((void**)&qkv,   g_qkv);
    cudaGetSymbolAddress((void**)&act1,  g_act1);
    cudaGetSymbolAddress((void**)&act2,  g_act2);
    cudaGetSymbolAddress((void**)&hid1,  g_hid1);
    cudaGetSymbolAddress((void**)&hid2,  g_hid2);
    cudaGetSymbolAddress((void**)&wq,    g_wq);
    cudaGetSymbolAddress((void**)&wp,    g_wp);
    cudaGetSymbolAddress((void**)&w1,    g_w1);
    cudaGetSymbolAddress((void**)&w2,    g_w2);

    const int SM192 = 3 * (256 + 192) * 80;  // 107520 -> 1 CTA/SM (120 CTAs)
    const int SM128 = 3 * (256 + 128) * 80;  // 92160  -> 2 CTAs/SM
    const int SM64  = 4 * (256 + 64)  * 80;  // 102400 -> 2 CTAs/SM
    cudaFuncSetAttribute(k_gemm_f16<192, 0, 3, 1>, cudaFuncAttributeMaxDynamicSharedMemorySize, SM192);
    cudaFuncSetAttribute(k_gemm_f16<128, 1, 3, 2>, cudaFuncAttributeMaxDynamicSharedMemorySize, SM128);
    cudaFuncSetAttribute(k_gemm_f16<64, 2, 4, 2>,  cudaFuncAttributeMaxDynamicSharedMemorySize, SM64);

    const int MT = M_PAD / 128;  // 10

    k_split_all<<<4096, 256>>>((const float4*)qkv_w, (const float4*)proj_w,
                               (const float4*)fc1_w, (const float4*)fc2_w);
    k_patchsel<<<BB * LL + BB, 256>>>(x, attn_mask, yids, conv_w, conv_b, pex, ytab, noise);
    k_gather_ln<<<MROWS, 256>>>(cls, pex, ln1_w, ln1_b);

    for (int l = 0; l < DEPTH; l++) {
        const float* qb  = qkv_b  + (size_t)l * 3 * DD;
        const float* pb  = proj_b + (size_t)l * DD;
        const float* l1w = ln1_w + l * DD; const float* l1b = ln1_b + l * DD;
        const float* l2w = ln2_w + l * DD; const float* l2b = ln2_b + l * DD;
        const float* f1b = fc1_b + (size_t)l * MLPD;
        const float* f2b = fc2_b + (size_t)l * DD;
        __half* lwq = wq + (size_t)l * 3 * DD * DD;
        __half* lwp = wp + (size_t)l * DD * DD;
        __half* lw1 = w1 + (size_t)l * MLPD * DD;
        __half* lw2 = w2 + (size_t)l * DD * MLPD;

        if (l > 0) k_ln_sp_w<<<MROWS / 8, 256>>>(carry, l1w, l1b);
        k_gemm_f16<192, 0, 3, 1><<<dim3(3 * DD / 192, MT), 256, SM192>>>(
            act1, act2, lwq, qb, nullptr, qkv, nullptr, nullptr, 3 * DD, DD);
        k_attn<<<BB * NHD, 256>>>(l);
        k_gemm_f16<64, 2, 4, 2><<<dim3(DD / 64, MT), 256, SM64>>>(
            act1, act2, lwp, pb, carry, carry, nullptr, nullptr, DD, DD);
        k_ln_sp_w<<<MROWS / 8, 256>>>(carry, l2w, l2b);
        k_gemm_f16<128, 1, 3, 2><<<dim3(MLPD / 128, MT), 256, SM128>>>(
            act1, act2, lw1, f1b, nullptr, nullptr, hid1, hid2, MLPD, DD);
        k_gemm_f16<64, 2, 4, 2><<<dim3(DD / 64, MT), 256, SM64>>>(
            hid1, hid2, lw2, f2b, carry, carry, nullptr, nullptr, DD, MLPD);
    }

    k_ln_w<<<MROWS / 8, 256>>>(carry, norm_w, norm_b, out);
}

// round 16
// speedup vs baseline: 1.1533x; 1.0028x over previous
#include <cuda_runtime.h>
#include <cuda_fp16.h>
#include <math.h>
#include <cstdint>

#define BB   16
#define HIN  12
#define WIN  2500
#define QQ   100
#define GW   25
#define LL   300
#define LEN_KEEP 75
#define NTOK 76
#define DD   768
#define DH   384
#define NHD  12
#define HD   64
#define DEPTH 12
#define MLPD 3072
#define SCALE 0.125f
#define EPS_LN 1e-5f
#define MROWS (BB * NTOK)     // 1216
#define M_PAD 1280            // 10 tiles of 128

#define QWN  (DEPTH * 3 * DD * DD)
#define PWN  (DEPTH * DD * DD)
#define F1N  (DEPTH * MLPD * DD)
#define F2N  (DEPTH * DD * MLPD)

// ---------------- scratch (device globals; no allocation allowed) -----------
__device__ float g_hfull[BB * LL * DD];
__device__ float g_carry[M_PAD * DD];
__device__ float g_qkv[M_PAD * 3 * DD];
__device__ int   g_idsk[BB * LEN_KEEP];
__device__ float g_m[BB * NTOK];
__device__ unsigned g_gmax;
__device__ unsigned g_cnt;
__device__ unsigned g_bar[32];

// split activations (fp16 main + fp16 residual)
__device__ __half g_act1[M_PAD * DD],   g_act2[M_PAD * DD];
__device__ __half g_hid1[M_PAD * MLPD], g_hid2[M_PAD * MLPD];
// fp16-rounded weights (single term)
__device__ __half g_wq[QWN];
__device__ __half g_wp[PWN];
__device__ __half g_w1[F1N];
__device__ __half g_w2[F2N];

// monotone float<->uint encoding for atomicMax on floats
__device__ __forceinline__ unsigned fenc(float f) {
    unsigned u = __float_as_uint(f);
    return (u & 0x80000000u) ? ~u : (u | 0x80000000u);
}
__device__ __forceinline__ float fdec(unsigned u) {
    return (u & 0x80000000u) ? __uint_as_float(u & 0x7fffffffu) : __uint_as_float(~u);
}

// ---------------- asm helpers -------------------------------------------------
#define CP_ASYNC16(dst, src) \
    asm volatile("cp.async.cg.shared.global [%0], [%1], 16;" :: "r"(dst), "l"(src))
#define CP_COMMIT() asm volatile("cp.async.commit_group;" ::: "memory")
#define LDSM4(r0, r1, r2, r3, addr)                                          \
    asm volatile("ldmatrix.sync.aligned.m8n8.x4.shared.b16 {%0,%1,%2,%3}, [%4];" \
        : "=r"(r0), "=r"(r1), "=r"(r2), "=r"(r3) : "r"(addr))

__device__ __forceinline__ void mma_fp16(float* d, const uint32_t* a,
                                         uint32_t b0, uint32_t b1) {
    asm volatile(
        "mma.sync.aligned.m16n8k16.row.col.f32.f16.f16.f32 "
        "{%0,%1,%2,%3}, {%4,%5,%6,%7}, {%8,%9}, {%0,%1,%2,%3};"
        : "+f"(d[0]), "+f"(d[1]), "+f"(d[2]), "+f"(d[3])
        : "r"(a[0]), "r"(a[1]), "r"(a[2]), "r"(a[3]), "r"(b0), "r"(b1));
}

__device__ __forceinline__ uint32_t packh(float v0, float v1) {
    __half2 h = __floats2half2_rn(v0, v1);
    return *(uint32_t*)&h;
}
__device__ __forceinline__ uint32_t packh_big(float v0, float v1, float& r0, float& r1) {
    __half h0 = __float2half_rn(v0);
    __half h1 = __float2half_rn(v1);
    r0 = v0 - __half2float(h0);
    r1 = v1 - __half2float(h1);
    __half2 h = __halves2half2(h0, h1);
    return *(uint32_t*)&h;
}

// ---------------- merged weight round kernel (single launch) ------------------
__global__ void k_split_all(const float4* __restrict__ qw, const float4* __restrict__ pw,
                            const float4* __restrict__ f1, const float4* __restrict__ f2) {
    const int q4 = QWN / 4, p4 = PWN / 4, a4 = F1N / 4, b4 = F2N / 4;
    const int total = q4 + p4 + a4 + b4;
    for (int i = blockIdx.x * blockDim.x + threadIdx.x; i < total;
         i += gridDim.x * blockDim.x) {
        const float4* src;
        __half* dst;
        int j = i;
        if (j < q4)               { src = qw; dst = g_wq; }
        else if ((j -= q4) < p4)  { src = pw; dst = g_wp; }
        else if ((j -= p4) < a4)  { src = f1; dst = g_w1; }
        else { j -= a4;             src = f2; dst = g_w2; }
        float4 v = src[j];
        *(uint2*)&dst[(size_t)j * 4] = make_uint2(packh(v.x, v.y), packh(v.z, v.w));
    }
}

// ---------------- fp16 two-term pipelined GEMM (+ optional fused LN) ----------
// MODE 0: bias -> fp32 C ; MODE 1: bias+gelu -> split fp16 ; MODE 2: bias+res -> C
// LNM  0: none ; 1: grid-barrier then LN(carry) -> split fp16 (+gmax reset)
//       2: grid-barrier then LN(carry) -> fp32 lnout
template <int BN, int MODE, int NST, int MAXCTA, int LNM>
__global__ void __launch_bounds__(256, MAXCTA)
k_gemm_f16(const __half* __restrict__ A1_g, const __half* __restrict__ A2_g,
           const __half* __restrict__ W_g,
           const float* __restrict__ bias, const float* __restrict__ res,
           float* __restrict__ C, __half* __restrict__ C1,
           __half* __restrict__ C2, int Ncols, int K,
           const float* __restrict__ lnw, const float* __restrict__ lnb,
           float* __restrict__ lnout, int slot) {
    extern __shared__ char sh[];
    const uint32_t STAGE = (256 + BN) * 80;
    const uint32_t AOFF = 128 * 80;
    uint32_t sbase = (uint32_t)__cvta_generic_to_shared(sh);

    const int tid = threadIdx.x;
    const int wid = tid >> 5, lane = tid & 31;
    const int g = lane >> 2, t = lane & 3;
    const int lrow = lane & 7, seg = lane >> 3;
    const int warp_m = wid & 3, warp_n = wid >> 2;
    const int wm0 = warp_m * 32;
    const int wn0 = warp_n * (BN / 2);
    const int m0 = blockIdx.y * 128, n0 = blockIdx.x * BN;
    const int NI = BN / 16;
    const int NCH = (256 + BN) * 4;
    const int nC = K >> 5;

    float acc[2][NI][4];
    #pragma unroll
    for (int mi = 0; mi < 2; mi++)
        #pragma unroll
        for (int ni = 0; ni < NI; ni++)
            #pragma unroll
            for (int j = 0; j < 4; j++) acc[mi][ni][j] = 0.f;

    auto load = [&](int c) {
        int k0 = c << 5;
        uint32_t base = sbase + (uint32_t)(c % NST) * STAGE;
        #pragma unroll
        for (int i = tid; i < NCH; i += 256) {
            const __half* gsrc;
            uint32_t dst;
            if (i < 512) {
                int row = i >> 2, j = i & 3;
                gsrc = A1_g + (size_t)(m0 + row) * K + k0 + j * 8;
                dst = base + row * 80 + j * 16;
            } else if (i < 1024) {
                int i2 = i - 512;
                int row = i2 >> 2, j = i2 & 3;
                gsrc = A2_g + (size_t)(m0 + row) * K + k0 + j * 8;
                dst = base + AOFF + row * 80 + j * 16;
            } else {
                int i2 = i - 1024;
                int row = i2 >> 2, j = i2 & 3;
                gsrc = W_g + (size_t)(n0 + row) * K + k0 + j * 8;
                dst = base + 2 * AOFF + row * 80 + j * 16;
            }
            CP_ASYNC16(dst, gsrc);
        }
        CP_COMMIT();
    };

    #pragma unroll
    for (int s = 0; s < NST - 1; s++) load(s);

    for (int c = 0; c < nC; c++) {
        if (c + NST - 1 < nC) {
            asm volatile("cp.async.wait_group %0;" :: "n"(NST - 2));
        } else {
            asm volatile("cp.async.wait_group 0;" ::: "memory");
        }
        __syncthreads();
        if (c + NST - 1 < nC) load(c + NST - 1);

        uint32_t base = sbase + (uint32_t)(c % NST) * STAGE;
        uint32_t a1B = base, a2B = base + AOFF;
        uint32_t wB = base + 2 * AOFF;

        #pragma unroll
        for (int ks = 0; ks < 2; ks++) {
            uint32_t x[2][4], y[2][4];
            #pragma unroll
            for (int mi = 0; mi < 2; mi++) {
                uint32_t off = (uint32_t)((wm0 + mi * 16 + (seg & 1) * 8 + lrow) * 80
                                          + ks * 32 + (seg >> 1) * 16);
                LDSM4(x[mi][0], x[mi][1], x[mi][2], x[mi][3], a1B + off);
                LDSM4(y[mi][0], y[mi][1], y[mi][2], y[mi][3], a2B + off);
            }
            #pragma unroll
            for (int np = 0; np < NI / 2; np++) {
                uint32_t off = (uint32_t)((wn0 + np * 16 + (seg >> 1) * 8 + lrow) * 80
                                          + ks * 32 + (seg & 1) * 16);
                uint32_t w0, w1, w2, w3;
                LDSM4(w0, w1, w2, w3, wB + off);
                int n1 = 2 * np, n2 = 2 * np + 1;
                #pragma unroll
                for (int mi = 0; mi < 2; mi++) mma_fp16(acc[mi][n1], x[mi], w0, w1);
                #pragma unroll
                for (int mi = 0; mi < 2; mi++) mma_fp16(acc[mi][n2], x[mi], w2, w3);
                #pragma unroll
                for (int mi = 0; mi < 2; mi++) mma_fp16(acc[mi][n1], y[mi], w0, w1);
                #pragma unroll
                for (int mi = 0; mi < 2; mi++) mma_fp16(acc[mi][n2], y[mi], w2, w3);
            }
        }
    }

    // epilogue
    #pragma unroll
    for (int mi = 0; mi < 2; mi++) {
        int r0 = m0 + wm0 + mi * 16 + g;
        int r1 = r0 + 8;
        #pragma unroll
        for (int ni = 0; ni < NI; ni++) {
            int n = n0 + wn0 + ni * 8 + 2 * t;
            float b0 = bias[n], b1 = bias[n + 1];
            float v0 = acc[mi][ni][0] + b0;
            float v1 = acc[mi][ni][1] + b1;
            float v2 = acc[mi][ni][2] + b0;
            float v3 = acc[mi][ni][3] + b1;
            if (MODE == 1) {
                v0 = 0.5f * v0 * (1.f + erff(v0 * 0.70710678118654752f));
                v1 = 0.5f * v1 * (1.f + erff(v1 * 0.70710678118654752f));
                v2 = 0.5f * v2 * (1.f + erff(v2 * 0.70710678118654752f));
                v3 = 0.5f * v3 * (1.f + erff(v3 * 0.70710678118654752f));
                float s0, s1, s2, s3;
                uint32_t m0w = packh_big(v0, v1, s0, s1);
                uint32_t m1w = packh_big(v2, v3, s2, s3);
                *(uint32_t*)&C1[(size_t)r0 * Ncols + n] = m0w;
                *(uint32_t*)&C1[(size_t)r1 * Ncols + n] = m1w;
                *(uint32_t*)&C2[(size_t)r0 * Ncols + n] = packh(s0, s1);
                *(uint32_t*)&C2[(size_t)r1 * Ncols + n] = packh(s2, s3);
            } else {
                if (MODE == 2) {
                    v0 += res[(size_t)r0 * Ncols + n];
                    v1 += res[(size_t)r0 * Ncols + n + 1];
                    v2 += res[(size_t)r1 * Ncols + n];
                    v3 += res[(size_t)r1 * Ncols + n + 1];
                }
                *(float2*)&C[(size_t)r0 * Ncols + n] = make_float2(v0, v1);
                *(float2*)&C[(size_t)r1 * Ncols + n] = make_float2(v2, v3);
            }
        }
    }

    // -------- fused layernorm (grid barrier over this launch's CTAs) --------
    if (LNM != 0) {
        __threadfence();
        __syncthreads();
        if (tid == 0) {
            unsigned nb = gridDim.x * gridDim.y;
            atomicAdd(&g_bar[slot], 1u);
            while (atomicAdd(&g_bar[slot], 0u) < nb) { }
            __threadfence();
        }
        __syncthreads();
        int bid = blockIdx.y * gridDim.x + blockIdx.x;
        if (LNM == 1 && bid == 0 && tid == 0) g_gmax = 0u;
        int nwarps = gridDim.x * gridDim.y * 8;
        for (int row = bid * 8 + wid; row < MROWS; row += nwarps) {
            const float4* p = (const float4*)(g_carry + (size_t)row * DD);
            float4 v[6];
            float s = 0.f;
            #pragma unroll
            for (int k = 0; k < 6; k++) {
                v[k] = p[lane + k * 32];
                s += v[k].x + v[k].y + v[k].z + v[k].w;
            }
            #pragma unroll
            for (int o = 16; o > 0; o >>= 1) s += __shfl_xor_sync(0xffffffffu, s, o);
            float mu = s * (1.f / DD);
            float var = 0.f;
            #pragma unroll
            for (int k = 0; k < 6; k++) {
                float a = v[k].x - mu, b2 = v[k].y - mu, c2 = v[k].z - mu, d2 = v[k].w - mu;
                var += a * a + b2 * b2 + c2 * c2 + d2 * d2;
            }
            #pragma unroll
            for (int o = 16; o > 0; o >>= 1) var += __shfl_xor_sync(0xffffffffu, var, o);
            float rstd = rsqrtf(var * (1.f / DD) + EPS_LN);
            const float4* w4 = (const float4*)lnw;
            const float4* b4 = (const float4*)lnb;
            #pragma unroll
            for (int k = 0; k < 6; k++) {
                int idx = lane + k * 32;
                float4 ww = w4[idx], bb = b4[idx];
                float x0 = (v[k].x - mu) * rstd * ww.x + bb.x;
                float x1 = (v[k].y - mu) * rstd * ww.y + bb.y;
                float x2 = (v[k].z - mu) * rstd * ww.z + bb.z;
                float x3 = (v[k].w - mu) * rstd * ww.w + bb.w;
                if (LNM == 1) {
                    float r0, r1, r2, r3;
                    uint32_t m1 = packh_big(x0, x1, r0, r1);
                    uint32_t m2 = packh_big(x2, x3, r2, r3);
                    size_t o2 = (size_t)row * DD + idx * 4;
                    *(uint2*)&g_act1[o2] = make_uint2(m1, m2);
                    *(uint2*)&g_act2[o2] = make_uint2(packh(r0, r1), packh(r2, r3));
                } else {
                    float4 r;
                    r.x = x0; r.y = x1; r.z = x2; r.w = x3;
                    ((float4*)(lnout + (size_t)row * DD))[idx] = r;
                }
            }
        }
    }
}

// ---------------- fused patchify + select (one launch) ------------------------
__global__ void k_patchsel(const float* __restrict__ x,
                           const float* __restrict__ attn_mask,
                           const int*   __restrict__ yids,
                           const float* __restrict__ conv_w,
                           const float* __restrict__ conv_b,
                           const float* __restrict__ pex,
                           const float* __restrict__ ytab,
                           const float* __restrict__ noise) {
    if (blockIdx.x >= BB * LL) {
        int b = blockIdx.x - BB * LL;
        __shared__ float ns[LL];
        __shared__ int ids[LL];
        __shared__ unsigned char keep[LL];
        for (int i = threadIdx.x; i < LL; i += blockDim.x) { ns[i] = noise[b * LL + i]; keep[i] = 0; }
        __syncthreads();
        for (int i = threadIdx.x; i < LL; i += blockDim.x) {
            float vi = ns[i];
            int r = 0;
            for (int j = 0; j < LL; j++) {
                float vj = ns[j];
                r += (vj < vi) || (vj == vi && j < i);
            }
            ids[r] = i;
        }
        __syncthreads();
        for (int t = threadIdx.x; t < LEN_KEEP; t += blockDim.x) {
            g_idsk[b * LEN_KEEP + t] = ids[t];
            keep[ids[t]] = 1;
        }
        __syncthreads();
        for (int i = threadIdx.x; i < LL; i += blockDim.x) {
            if (keep[i]) {
                int pos = 0;
                for (int j = 0; j < i; j++) pos += keep[j];
                g_m[b * NTOK + 1 + pos] = attn_mask[b * LL + i];
            }
        }
        if (threadIdx.x == 0) g_m[b * NTOK] = 1.f;
        return;
    }
    int bl = blockIdx.x;
    int b = bl / LL, l = bl % LL;
    int gh = l / GW, gw = l % GW;
    __shared__ float patch[QQ];
    const float* xrow = x + ((size_t)b * HIN + gh) * WIN + gw * QQ;
    for (int i = threadIdx.x; i < QQ; i += blockDim.x) patch[i] = xrow[i];
    __syncthreads();
    float am = attn_mask[b * LL + l];
    int yid = yids[b * LL + l];
    for (int d = threadIdx.x; d < DD; d += blockDim.x) {
        const float* w = conv_w + d * QQ;
        float acc = 0.f;
        #pragma unroll 4
        for (int q = 0; q < QQ; q++) acc += patch[q] * w[q];
        acc += conv_b[d];
        if (d < DH) acc += ytab[yid * DH + d];
        else        acc += am * pex[(gw + 1) * DH + (d - DH)];
        g_hfull[((size_t)b * LL + l) * DD + d] = acc;
    }
}

// ---------------- fused gather + layer-0 LN1 + barrier/cnt resets -------------
__global__ void k_gather_ln(const float* __restrict__ cls_token,
                            const float* __restrict__ pex,
                            const float* __restrict__ w,
                            const float* __restrict__ bias) {
    int bt = blockIdx.x;
    int b = bt / NTOK, t = bt % NTOK;
    if (bt == 0 && threadIdx.x == 0) {
        g_gmax = 0u; g_cnt = 0u;
        for (int i = 0; i < 32; i++) g_bar[i] = 0u;
    }
    __shared__ float row[DD];
    __shared__ float red[256];
    float* outp = g_carry + (size_t)bt * DD;
    if (t == 0) {
        for (int d = threadIdx.x; d < DD; d += 256) {
            float v = cls_token[d] + (d >= DH ? pex[d - DH] : 0.f);
            row[d] = v; outp[d] = v;
        }
    } else {
        int l = g_idsk[b * LEN_KEEP + (t - 1)];
        const float* src = g_hfull + ((size_t)b * LL + l) * DD;
        for (int d = threadIdx.x; d < DD; d += 256) {
            float v = src[d];
            row[d] = v; outp[d] = v;
        }
    }
    __syncthreads();
    float s = 0.f;
    for (int d = threadIdx.x; d < DD; d += 256) s += row[d];
    red[threadIdx.x] = s; __syncthreads();
    for (int o = 128; o > 0; o >>= 1) {
        if (threadIdx.x < o) red[threadIdx.x] += red[threadIdx.x + o];
        __syncthreads();
    }
    float mu = red[0] * (1.f / DD);
    __syncthreads();
    float v = 0.f;
    for (int d = threadIdx.x; d < DD; d += 256) { float u = row[d] - mu; v += u * u; }
    red[threadIdx.x] = v; __syncthreads();
    for (int o = 128; o > 0; o >>= 1) {
        if (threadIdx.x < o) red[threadIdx.x] += red[threadIdx.x + o];
        __syncthreads();
    }
    float rstd = rsqrtf(red[0] * (1.f / DD) + EPS_LN);
    for (int d = threadIdx.x; d < DD; d += 256) {
        float val = (row[d] - mu) * rstd * w[d] + bias[d];
        __half h = __float2half_rn(val);
        g_act1[(size_t)bt * DD + d] = h;
        g_act2[(size_t)bt * DD + d] = __float2half_rn(val - __half2float(h));
    }
}

// ---------------- fused attention: scores + global max (grid barrier) + AV ----
__global__ void __launch_bounds__(256)
k_attn(int layer) {
    int bh = blockIdx.x;
    int h = bh % NHD, b = bh / NHD;
    __shared__ float4 Q4[NTOK][17];   // reused for V after scores
    __shared__ float4 K4[NTOK][17];
    __shared__ float Psh[NTOK][77];
    __shared__ float msh[NTOK];
    __shared__ float wred[8];
    __shared__ float rsum[NTOK];
    __shared__ float sh_gmx;
    int tid = threadIdx.x;
    const float4* qkv4 = (const float4*)g_qkv;
    for (int idx = tid; idx < NTOK * 16; idx += 256) {
        int r = idx >> 4, d4 = idx & 15;
        size_t base = (size_t)(b * NTOK + r) * (3 * DD / 4) + h * 16 + d4;
        Q4[r][d4] = qkv4[base];
        K4[r][d4] = qkv4[base + DD / 4];
    }
    for (int i = tid; i < NTOK; i += 256) msh[i] = g_m[b * NTOK + i];
    __syncthreads();
    int w = tid >> 5, lane = tid & 31;
    float lmax = -3.4e38f;
    for (int n = w; n < NTOK; n += 8) {
        float mn = msh[n];
        for (int m = lane; m < NTOK; m += 32) {
            float dot = 0.f;
            #pragma unroll
            for (int d4 = 0; d4 < 16; d4++) {
                float4 q = Q4[n][d4];
                float4 k = K4[m][d4];
                dot = fmaf(q.x, k.x, dot);
                dot = fmaf(q.y, k.y, dot);
                dot = fmaf(q.z, k.z, dot);
                dot = fmaf(q.w, k.w, dot);
            }
            float logit = dot * SCALE;
            if (mn * msh[m] == 0.f) logit = -INFINITY;
            else lmax = fmaxf(lmax, logit);
            Psh[n][m] = logit;
        }
    }
    #pragma unroll
    for (int o = 16; o > 0; o >>= 1)
        lmax = fmaxf(lmax, __shfl_xor_sync(0xffffffffu, lmax, o));
    if (lane == 0) wred[w] = lmax;
    __syncthreads();
    if (tid == 0) {
        float bm = wred[0];
        #pragma unroll
        for (int i = 1; i < 8; i++) bm = fmaxf(bm, wred[i]);
        if (bm > -3.3e38f) atomicMax(&g_gmax, fenc(bm));
        __threadfence();
        atomicAdd(&g_cnt, 1u);
    }
    __syncthreads();   // scores done: safe to overwrite Q4 with V
    for (int idx = tid; idx < NTOK * 16; idx += 256) {
        int r = idx >> 4, d4 = idx & 15;
        Q4[r][d4] = qkv4[(size_t)(b * NTOK + r) * (3 * DD / 4) + 2 * DD / 4 + h * 16 + d4];
    }
    if (tid == 0) {
        unsigned target = 192u * (unsigned)(layer + 1);
        while (atomicAdd(&g_cnt, 0u) < target) { }
        sh_gmx = fdec(atomicAdd(&g_gmax, 0u));
    }
    __syncthreads();
    float gmx = sh_gmx;
    for (int n = w; n < NTOK; n += 8) {
        float s = 0.f;
        for (int m = lane; m < NTOK; m += 32) {
            float e = expf(Psh[n][m] - gmx);
            Psh[n][m] = e;
            s += e;
        }
        #pragma unroll
        for (int o = 16; o > 0; o >>= 1) s += __shfl_xor_sync(0xffffffffu, s, o);
        if (lane == 0) rsum[n] = s;
    }
    __syncthreads();
    int d4 = lane & 15, par = lane >> 4;
    for (int n = w; n < NTOK; n += 8) {
        float inv = 1.f / (rsum[n] + 1e-9f);
        float4 acc = make_float4(0.f, 0.f, 0.f, 0.f);
        for (int m = par; m < NTOK; m += 2) {
            float p = Psh[n][m];
            float4 v = Q4[m][d4];
            acc.x = fmaf(p, v.x, acc.x);
            acc.y = fmaf(p, v.y, acc.y);
            acc.z = fmaf(p, v.z, acc.z);
            acc.w = fmaf(p, v.w, acc.w);
        }
        acc.x += __shfl_down_sync(0xffffffffu, acc.x, 16);
        acc.y += __shfl_down_sync(0xffffffffu, acc.y, 16);
        acc.z += __shfl_down_sync(0xffffffffu, acc.z, 16);
        acc.w += __shfl_down_sync(0xffffffffu, acc.w, 16);
        if (par == 0) {
            size_t o2 = (size_t)(b * NTOK + n) * DD + h * HD + d4 * 4;
            float vals[4] = {acc.x * inv, acc.y * inv, acc.z * inv, acc.w * inv};
            float r0, r1, r2, r3;
            uint32_t m1 = packh_big(vals[0], vals[1], r0, r1);
            uint32_t m2 = packh_big(vals[2], vals[3], r2, r3);
            *(uint2*)&g_act1[o2] = make_uint2(m1, m2);
            *(uint2*)&g_act2[o2] = make_uint2(packh(r0, r1), packh(r2, r3));
        }
    }
}

// ---------------- launch -----------------------------------------------------
extern "C" void kernel_launch(void* const* d_in, const int* in_sizes, int n_in,
                              void* d_out, int out_size) {
    const float* x         = (const float*)d_in[0];
    const float* attn_mask = (const float*)d_in[1];
    const int*   yids      = (const int*)  d_in[2];
    const float* noise     = (const float*)d_in[3];
    const float* conv_w    = (const float*)d_in[4];
    const float* conv_b    = (const float*)d_in[5];
    const float* pex       = (const float*)d_in[6];
    const float* ytab      = (const float*)d_in[7];
    const float* cls       = (const float*)d_in[8];
    const float* qkv_w     = (const float*)d_in[9];
    const float* qkv_b     = (const float*)d_in[10];
    const float* proj_w    = (const float*)d_in[11];
    const float* proj_b    = (const float*)d_in[12];
    const float* ln1_w     = (const float*)d_in[13];
    const float* ln1_b     = (const float*)d_in[14];
    const float* ln2_w     = (const float*)d_in[15];
    const float* ln2_b     = (const float*)d_in[16];
    const float* fc1_w     = (const float*)d_in[17];
    const float* fc1_b     = (const float*)d_in[18];
    const float* fc2_w     = (const float*)d_in[19];
    const float* fc2_b     = (const float*)d_in[20];
    const float* norm_w    = (const float*)d_in[21];
    const float* norm_b    = (const float*)d_in[22];
    float* out = (float*)d_out;

    float *carry, *qkv;
    __half *act1, *act2, *hid1, *hid2, *wq, *wp, *w1, *w2;
    cudaGetSymbolAddress((void**)&carry, g_carry);
    cudaGetSymbolAddress((void**)&qkv,   g_qkv);
    cudaGetSymbolAddress((void**)&act1,  g_act1);
    cudaGetSymbolAddress((void**)&act2,  g_act2);
    cudaGetSymbolAddress((void**)&hid1,  g_hid1);
    cudaGetSymbolAddress((void**)&hid2,  g_hid2);
    cudaGetSymbolAddress((void**)&wq,    g_wq);
    cudaGetSymbolAddress((void**)&wp,    g_wp);
    cudaGetSymbolAddress((void**)&w1,    g_w1);
    cudaGetSymbolAddress((void**)&w2,    g_w2);

    const int SM192 = 3 * (256 + 192) * 80;  // 107520 -> 1 CTA/SM (120 CTAs)
    const int SM128 = 3 * (256 + 128) * 80;  // 92160  -> 2 CTAs/SM
    const int SM64  = 4 * (256 + 64)  * 80;  // 102400
    cudaFuncSetAttribute(k_gemm_f16<192, 0, 3, 1, 0>, cudaFuncAttributeMaxDynamicSharedMemorySize, SM192);
    cudaFuncSetAttribute(k_gemm_f16<128, 1, 3, 2, 0>, cudaFuncAttributeMaxDynamicSharedMemorySize, SM128);
    cudaFuncSetAttribute(k_gemm_f16<64, 2, 4, 2, 1>,  cudaFuncAttributeMaxDynamicSharedMemorySize, SM64);
    cudaFuncSetAttribute(k_gemm_f16<64, 2, 4, 2, 2>,  cudaFuncAttributeMaxDynamicSharedMemorySize, SM64);

    const int MT = M_PAD / 128;  // 10

    k_split_all<<<4096, 256>>>((const float4*)qkv_w, (const float4*)proj_w,
                               (const float4*)fc1_w, (const float4*)fc2_w);
    k_patchsel<<<BB * LL + BB, 256>>>(x, attn_mask, yids, conv_w, conv_b, pex, ytab, noise);
    k_gather_ln<<<MROWS, 256>>>(cls, pex, ln1_w, ln1_b);

    for (int l = 0; l < DEPTH; l++) {
        const float* qb  = qkv_b  + (size_t)l * 3 * DD;
        const float* pb  = proj_b + (size_t)l * DD;
        const float* l2w = ln2_w + l * DD; const float* l2b = ln2_b + l * DD;
        const float* f1b = fc1_b + (size_t)l * MLPD;
        const float* f2b = fc2_b + (size_t)l * DD;
        __half* lwq = wq + (size_t)l * 3 * DD * DD;
        __half* lwp = wp + (size_t)l * DD * DD;
        __half* lw1 = w1 + (size_t)l * MLPD * DD;
        __half* lw2 = w2 + (size_t)l * DD * MLPD;

        k_gemm_f16<192, 0, 3, 1, 0><<<dim3(3 * DD / 192, MT), 256, SM192>>>(
            act1, act2, lwq, qb, nullptr, qkv, nullptr, nullptr, 3 * DD, DD,
            nullptr, nullptr, nullptr, 0);
        k_attn<<<BB * NHD, 256>>>(l);
        // proj + fused LN2 (split fp16 out for fc1)
        k_gemm_f16<64, 2, 4, 2, 1><<<dim3(DD / 64, MT), 256, SM64>>>(
            act1, act2, lwp, pb, carry, carry, nullptr, nullptr, DD, DD,
            l2w, l2b, nullptr, 2 * l);
        k_gemm_f16<128, 1, 3, 2, 0><<<dim3(MLPD / 128, MT), 256, SM128>>>(
            act1, act2, lw1, f1b, nullptr, nullptr, hid1, hid2, MLPD, DD,
            nullptr, nullptr, nullptr, 0);
        if (l < DEPTH - 1) {
            // fc2 + fused LN1 of next layer (split fp16; resets gmax)
            const float* n1w = ln1_w + (l + 1) * DD;
            const float* n1b = ln1_b + (l + 1) * DD;
            k_gemm_f16<64, 2, 4, 2, 1><<<dim3(DD / 64, MT), 256, SM64>>>(
                hid1, hid2, lw2, f2b, carry, carry, nullptr, nullptr, DD, MLPD,
                n1w, n1b, nullptr, 2 * l + 1);
        } else {
            // last fc2 + fused final norm -> out (fp32)
            k_gemm_f16<64, 2, 4, 2, 2><<<dim3(DD / 64, MT), 256, SM64>>>(
                hid1, hid2, lw2, f2b, carry, carry, nullptr, nullptr, DD, MLPD,
                norm_w, norm_b, out, 2 * l + 1);
        }
    }
}

// round 17
// speedup vs baseline: 1.2921x; 1.1203x over previous
#include <cuda_runtime.h>
#include <cuda_fp16.h>
#include <math.h>
#include <cstdint>

#define BB   16
#define HIN  12
#define WIN  2500
#define QQ   100
#define GW   25
#define LL   300
#define LEN_KEEP 75
#define NTOK 76
#define DD   768
#define DH   384
#define NHD  12
#define HD   64
#define DEPTH 12
#define MLPD 3072
#define SCALE 0.125f
#define EPS_LN 1e-5f
#define MROWS (BB * NTOK)     // 1216
#define M_PAD 1280            // 10 tiles of 128

#define QWN  (DEPTH * 3 * DD * DD)
#define PWN  (DEPTH * DD * DD)
#define F1N  (DEPTH * MLPD * DD)
#define F2N  (DEPTH * DD * MLPD)

// ---------------- scratch (device globals; no allocation allowed) -----------
__device__ float g_hfull[BB * LL * DD];
__device__ float g_carry[M_PAD * DD];
__device__ float g_qkv[M_PAD * 3 * DD];
__device__ int   g_idsk[BB * LEN_KEEP];
__device__ float g_m[BB * NTOK];
__device__ unsigned g_gmax;
__device__ unsigned g_cnt;
__device__ unsigned g_bar[32];

// split activations (fp16 main + fp16 residual)
__device__ __half g_act1[M_PAD * DD],   g_act2[M_PAD * DD];
__device__ __half g_hid1[M_PAD * MLPD], g_hid2[M_PAD * MLPD];
// fp16-rounded weights (single term)
__device__ __half g_wq[QWN];
__device__ __half g_wp[PWN];
__device__ __half g_w1[F1N];
__device__ __half g_w2[F2N];

// monotone float<->uint encoding for atomicMax on floats
__device__ __forceinline__ unsigned fenc(float f) {
    unsigned u = __float_as_uint(f);
    return (u & 0x80000000u) ? ~u : (u | 0x80000000u);
}
__device__ __forceinline__ float fdec(unsigned u) {
    return (u & 0x80000000u) ? __uint_as_float(u & 0x7fffffffu) : __uint_as_float(~u);
}

// ---------------- asm helpers -------------------------------------------------
#define CP_ASYNC16(dst, src) \
    asm volatile("cp.async.cg.shared.global [%0], [%1], 16;" :: "r"(dst), "l"(src))
#define CP_COMMIT() asm volatile("cp.async.commit_group;" ::: "memory")
#define LDSM4(r0, r1, r2, r3, addr)                                          \
    asm volatile("ldmatrix.sync.aligned.m8n8.x4.shared.b16 {%0,%1,%2,%3}, [%4];" \
        : "=r"(r0), "=r"(r1), "=r"(r2), "=r"(r3) : "r"(addr))

__device__ __forceinline__ void mma_fp16(float* d, const uint32_t* a,
                                         uint32_t b0, uint32_t b1) {
    asm volatile(
        "mma.sync.aligned.m16n8k16.row.col.f32.f16.f16.f32 "
        "{%0,%1,%2,%3}, {%4,%5,%6,%7}, {%8,%9}, {%0,%1,%2,%3};"
        : "+f"(d[0]), "+f"(d[1]), "+f"(d[2]), "+f"(d[3])
        : "r"(a[0]), "r"(a[1]), "r"(a[2]), "r"(a[3]), "r"(b0), "r"(b1));
}

__device__ __forceinline__ uint32_t packh(float v0, float v1) {
    __half2 h = __floats2half2_rn(v0, v1);
    return *(uint32_t*)&h;
}
__device__ __forceinline__ uint32_t packh_big(float v0, float v1, float& r0, float& r1) {
    __half h0 = __float2half_rn(v0);
    __half h1 = __float2half_rn(v1);
    r0 = v0 - __half2float(h0);
    r1 = v1 - __half2float(h1);
    __half2 h = __halves2half2(h0, h1);
    return *(uint32_t*)&h;
}

// ---------------- merged weight round kernel (single launch) ------------------
__global__ void k_split_all(const float4* __restrict__ qw, const float4* __restrict__ pw,
                            const float4* __restrict__ f1, const float4* __restrict__ f2) {
    const int q4 = QWN / 4, p4 = PWN / 4, a4 = F1N / 4, b4 = F2N / 4;
    const int total = q4 + p4 + a4 + b4;
    for (int i = blockIdx.x * blockDim.x + threadIdx.x; i < total;
         i += gridDim.x * blockDim.x) {
        const float4* src;
        __half* dst;
        int j = i;
        if (j < q4)               { src = qw; dst = g_wq; }
        else if ((j -= q4) < p4)  { src = pw; dst = g_wp; }
        else if ((j -= p4) < a4)  { src = f1; dst = g_w1; }
        else { j -= a4;             src = f2; dst = g_w2; }
        float4 v = src[j];
        *(uint2*)&dst[(size_t)j * 4] = make_uint2(packh(v.x, v.y), packh(v.z, v.w));
    }
}

// ---------------- fp16 pipelined GEMM (TERMS=2: a1+a2 ; TERMS=1: a1 only) -----
// MODE 0: bias -> fp32 C ; MODE 1: bias+gelu -> split fp16 ; MODE 2: bias+res -> C
// LNM  0: none ; 1: grid-barrier then LN(carry) -> split fp16 (+gmax reset)
//      2: grid-barrier then LN(carry) -> fp32 lnout
template <int BN, int MODE, int NST, int MAXCTA, int LNM, int TERMS>
__global__ void __launch_bounds__(256, MAXCTA)
k_gemm_f16(const __half* __restrict__ A1_g, const __half* __restrict__ A2_g,
           const __half* __restrict__ W_g,
           const float* __restrict__ bias, const float* __restrict__ res,
           float* __restrict__ C, __half* __restrict__ C1,
           __half* __restrict__ C2, int Ncols, int K,
           const float* __restrict__ lnw, const float* __restrict__ lnb,
           float* __restrict__ lnout, int slot) {
    extern __shared__ char sh[];
    const uint32_t STAGE = (128 * TERMS + BN) * 80;
    const uint32_t AOFF = 128 * 80;
    uint32_t sbase = (uint32_t)__cvta_generic_to_shared(sh);

    const int tid = threadIdx.x;
    const int wid = tid >> 5, lane = tid & 31;
    const int g = lane >> 2, t = lane & 3;
    const int lrow = lane & 7, seg = lane >> 3;
    const int warp_m = wid & 3, warp_n = wid >> 2;
    const int wm0 = warp_m * 32;
    const int wn0 = warp_n * (BN / 2);
    const int m0 = blockIdx.y * 128, n0 = blockIdx.x * BN;
    const int NI = BN / 16;
    const int NCH = (128 * TERMS + BN) * 4;
    const int nC = K >> 5;

    float acc[2][NI][4];
    #pragma unroll
    for (int mi = 0; mi < 2; mi++)
        #pragma unroll
        for (int ni = 0; ni < NI; ni++)
            #pragma unroll
            for (int j = 0; j < 4; j++) acc[mi][ni][j] = 0.f;

    auto load = [&](int c) {
        int k0 = c << 5;
        uint32_t base = sbase + (uint32_t)(c % NST) * STAGE;
        #pragma unroll
        for (int i = tid; i < NCH; i += 256) {
            const __half* gsrc;
            uint32_t dst;
            if (i < 512) {
                int row = i >> 2, j = i & 3;
                gsrc = A1_g + (size_t)(m0 + row) * K + k0 + j * 8;
                dst = base + row * 80 + j * 16;
            } else if (TERMS == 2 && i < 1024) {
                int i2 = i - 512;
                int row = i2 >> 2, j = i2 & 3;
                gsrc = A2_g + (size_t)(m0 + row) * K + k0 + j * 8;
                dst = base + AOFF + row * 80 + j * 16;
            } else {
                int i2 = i - 512 * TERMS;
                int row = i2 >> 2, j = i2 & 3;
                gsrc = W_g + (size_t)(n0 + row) * K + k0 + j * 8;
                dst = base + TERMS * AOFF + row * 80 + j * 16;
            }
            CP_ASYNC16(dst, gsrc);
        }
        CP_COMMIT();
    };

    #pragma unroll
    for (int s = 0; s < NST - 1; s++) load(s);

    for (int c = 0; c < nC; c++) {
        if (c + NST - 1 < nC) {
            asm volatile("cp.async.wait_group %0;" :: "n"(NST - 2));
        } else {
            asm volatile("cp.async.wait_group 0;" ::: "memory");
        }
        __syncthreads();
        if (c + NST - 1 < nC) load(c + NST - 1);

        uint32_t base = sbase + (uint32_t)(c % NST) * STAGE;
        uint32_t a1B = base, a2B = base + AOFF;
        uint32_t wB = base + TERMS * AOFF;

        #pragma unroll
        for (int ks = 0; ks < 2; ks++) {
            uint32_t x[2][4], y[2][4];
            #pragma unroll
            for (int mi = 0; mi < 2; mi++) {
                uint32_t off = (uint32_t)((wm0 + mi * 16 + (seg & 1) * 8 + lrow) * 80
                                          + ks * 32 + (seg >> 1) * 16);
                LDSM4(x[mi][0], x[mi][1], x[mi][2], x[mi][3], a1B + off);
                if (TERMS == 2)
                    LDSM4(y[mi][0], y[mi][1], y[mi][2], y[mi][3], a2B + off);
            }
            #pragma unroll
            for (int np = 0; np < NI / 2; np++) {
                uint32_t off = (uint32_t)((wn0 + np * 16 + (seg >> 1) * 8 + lrow) * 80
                                          + ks * 32 + (seg & 1) * 16);
                uint32_t w0, w1, w2, w3;
                LDSM4(w0, w1, w2, w3, wB + off);
                int n1 = 2 * np, n2 = 2 * np + 1;
                #pragma unroll
                for (int mi = 0; mi < 2; mi++) mma_fp16(acc[mi][n1], x[mi], w0, w1);
                #pragma unroll
                for (int mi = 0; mi < 2; mi++) mma_fp16(acc[mi][n2], x[mi], w2, w3);
                if (TERMS == 2) {
                    #pragma unroll
                    for (int mi = 0; mi < 2; mi++) mma_fp16(acc[mi][n1], y[mi], w0, w1);
                    #pragma unroll
                    for (int mi = 0; mi < 2; mi++) mma_fp16(acc[mi][n2], y[mi], w2, w3);
                }
            }
        }
    }

    // epilogue
    #pragma unroll
    for (int mi = 0; mi < 2; mi++) {
        int r0 = m0 + wm0 + mi * 16 + g;
        int r1 = r0 + 8;
        #pragma unroll
        for (int ni = 0; ni < NI; ni++) {
            int n = n0 + wn0 + ni * 8 + 2 * t;
            float b0 = bias[n], b1 = bias[n + 1];
            float v0 = acc[mi][ni][0] + b0;
            float v1 = acc[mi][ni][1] + b1;
            float v2 = acc[mi][ni][2] + b0;
            float v3 = acc[mi][ni][3] + b1;
            if (MODE == 1) {
                v0 = 0.5f * v0 * (1.f + erff(v0 * 0.70710678118654752f));
                v1 = 0.5f * v1 * (1.f + erff(v1 * 0.70710678118654752f));
                v2 = 0.5f * v2 * (1.f + erff(v2 * 0.70710678118654752f));
                v3 = 0.5f * v3 * (1.f + erff(v3 * 0.70710678118654752f));
                float s0, s1, s2, s3;
                uint32_t m0w = packh_big(v0, v1, s0, s1);
                uint32_t m1w = packh_big(v2, v3, s2, s3);
                *(uint32_t*)&C1[(size_t)r0 * Ncols + n] = m0w;
                *(uint32_t*)&C1[(size_t)r1 * Ncols + n] = m1w;
                *(uint32_t*)&C2[(size_t)r0 * Ncols + n] = packh(s0, s1);
                *(uint32_t*)&C2[(size_t)r1 * Ncols + n] = packh(s2, s3);
            } else {
                if (MODE == 2) {
                    v0 += res[(size_t)r0 * Ncols + n];
                    v1 += res[(size_t)r0 * Ncols + n + 1];
                    v2 += res[(size_t)r1 * Ncols + n];
                    v3 += res[(size_t)r1 * Ncols + n + 1];
                }
                *(float2*)&C[(size_t)r0 * Ncols + n] = make_float2(v0, v1);
                *(float2*)&C[(size_t)r1 * Ncols + n] = make_float2(v2, v3);
            }
        }
    }

    // -------- fused layernorm (grid barrier over this launch's CTAs) --------
    if (LNM != 0) {
        __threadfence();
        __syncthreads();
        if (tid == 0) {
            unsigned nb = gridDim.x * gridDim.y;
            atomicAdd(&g_bar[slot], 1u);
            while (atomicAdd(&g_bar[slot], 0u) < nb) { }
            __threadfence();
        }
        __syncthreads();
        int bid = blockIdx.y * gridDim.x + blockIdx.x;
        if (LNM == 1 && bid == 0 && tid == 0) g_gmax = 0u;
        int nwarps = gridDim.x * gridDim.y * 8;
        for (int row = bid * 8 + wid; row < MROWS; row += nwarps) {
            const float4* p = (const float4*)(g_carry + (size_t)row * DD);
            float4 v[6];
            float s = 0.f;
            #pragma unroll
            for (int k = 0; k < 6; k++) {
                v[k] = p[lane + k * 32];
                s += v[k].x + v[k].y + v[k].z + v[k].w;
            }
            #pragma unroll
            for (int o = 16; o > 0; o >>= 1) s += __shfl_xor_sync(0xffffffffu, s, o);
            float mu = s * (1.f / DD);
            float var = 0.f;
            #pragma unroll
            for (int k = 0; k < 6; k++) {
                float a = v[k].x - mu, b2 = v[k].y - mu, c2 = v[k].z - mu, d2 = v[k].w - mu;
                var += a * a + b2 * b2 + c2 * c2 + d2 * d2;
            }
            #pragma unroll
            for (int o = 16; o > 0; o >>= 1) var += __shfl_xor_sync(0xffffffffu, var, o);
            float rstd = rsqrtf(var * (1.f / DD) + EPS_LN);
            const float4* w4 = (const float4*)lnw;
            const float4* b4 = (const float4*)lnb;
            #pragma unroll
            for (int k = 0; k < 6; k++) {
                int idx = lane + k * 32;
                float4 ww = w4[idx], bb = b4[idx];
                float x0 = (v[k].x - mu) * rstd * ww.x + bb.x;
                float x1 = (v[k].y - mu) * rstd * ww.y + bb.y;
                float x2 = (v[k].z - mu) * rstd * ww.z + bb.z;
                float x3 = (v[k].w - mu) * rstd * ww.w + bb.w;
                if (LNM == 1) {
                    float r0, r1, r2, r3;
                    uint32_t m1 = packh_big(x0, x1, r0, r1);
                    uint32_t m2 = packh_big(x2, x3, r2, r3);
                    size_t o2 = (size_t)row * DD + idx * 4;
                    *(uint2*)&g_act1[o2] = make_uint2(m1, m2);
                    *(uint2*)&g_act2[o2] = make_uint2(packh(r0, r1), packh(r2, r3));
                } else {
                    float4 r;
                    r.x = x0; r.y = x1; r.z = x2; r.w = x3;
                    ((float4*)(lnout + (size_t)row * DD))[idx] = r;
                }
            }
        }
    }
}

// ---------------- fused patchify + select (one launch) ------------------------
__global__ void k_patchsel(const float* __restrict__ x,
                           const float* __restrict__ attn_mask,
                           const int*   __restrict__ yids,
                           const float* __restrict__ conv_w,
                           const float* __restrict__ conv_b,
                           const float* __restrict__ pex,
                           const float* __restrict__ ytab,
                           const float* __restrict__ noise) {
    if (blockIdx.x >= BB * LL) {
        int b = blockIdx.x - BB * LL;
        __shared__ float ns[LL];
        __shared__ int ids[LL];
        __shared__ unsigned char keep[LL];
        for (int i = threadIdx.x; i < LL; i += blockDim.x) { ns[i] = noise[b * LL + i]; keep[i] = 0; }
        __syncthreads();
        for (int i = threadIdx.x; i < LL; i += blockDim.x) {
            float vi = ns[i];
            int r = 0;
            for (int j = 0; j < LL; j++) {
                float vj = ns[j];
                r += (vj < vi) || (vj == vi && j < i);
            }
            ids[r] = i;
        }
        __syncthreads();
        for (int t = threadIdx.x; t < LEN_KEEP; t += blockDim.x) {
            g_idsk[b * LEN_KEEP + t] = ids[t];
            keep[ids[t]] = 1;
        }
        __syncthreads();
        for (int i = threadIdx.x; i < LL; i += blockDim.x) {
            if (keep[i]) {
                int pos = 0;
                for (int j = 0; j < i; j++) pos += keep[j];
                g_m[b * NTOK + 1 + pos] = attn_mask[b * LL + i];
            }
        }
        if (threadIdx.x == 0) g_m[b * NTOK] = 1.f;
        return;
    }
    int bl = blockIdx.x;
    int b = bl / LL, l = bl % LL;
    int gh = l / GW, gw = l % GW;
    __shared__ float patch[QQ];
    const float* xrow = x + ((size_t)b * HIN + gh) * WIN + gw * QQ;
    for (int i = threadIdx.x; i < QQ; i += blockDim.x) patch[i] = xrow[i];
    __syncthreads();
    float am = attn_mask[b * LL + l];
    int yid = yids[b * LL + l];
    for (int d = threadIdx.x; d < DD; d += blockDim.x) {
        const float* w = conv_w + d * QQ;
        float acc = 0.f;
        #pragma unroll 4
        for (int q = 0; q < QQ; q++) acc += patch[q] * w[q];
        acc += conv_b[d];
        if (d < DH) acc += ytab[yid * DH + d];
        else        acc += am * pex[(gw + 1) * DH + (d - DH)];
        g_hfull[((size_t)b * LL + l) * DD + d] = acc;
    }
}

// ---------------- fused gather + layer-0 LN1 + barrier/cnt resets -------------
__global__ void k_gather_ln(const float* __restrict__ cls_token,
                            const float* __restrict__ pex,
                            const float* __restrict__ w,
                            const float* __restrict__ bias) {
    int bt = blockIdx.x;
    int b = bt / NTOK, t = bt % NTOK;
    if (bt == 0 && threadIdx.x == 0) {
        g_gmax = 0u; g_cnt = 0u;
        for (int i = 0; i < 32; i++) g_bar[i] = 0u;
    }
    __shared__ float row[DD];
    __shared__ float red[256];
    float* outp = g_carry + (size_t)bt * DD;
    if (t == 0) {
        for (int d = threadIdx.x; d < DD; d += 256) {
            float v = cls_token[d] + (d >= DH ? pex[d - DH] : 0.f);
            row[d] = v; outp[d] = v;
        }
    } else {
        int l = g_idsk[b * LEN_KEEP + (t - 1)];
        const float* src = g_hfull + ((size_t)b * LL + l) * DD;
        for (int d = threadIdx.x; d < DD; d += 256) {
            float v = src[d];
            row[d] = v; outp[d] = v;
        }
    }
    __syncthreads();
    float s = 0.f;
    for (int d = threadIdx.x; d < DD; d += 256) s += row[d];
    red[threadIdx.x] = s; __syncthreads();
    for (int o = 128; o > 0; o >>= 1) {
        if (threadIdx.x < o) red[threadIdx.x] += red[threadIdx.x + o];
        __syncthreads();
    }
    float mu = red[0] * (1.f / DD);
    __syncthreads();
    float v = 0.f;
    for (int d = threadIdx.x; d < DD; d += 256) { float u = row[d] - mu; v += u * u; }
    red[threadIdx.x] = v; __syncthreads();
    for (int o = 128; o > 0; o >>= 1) {
        if (threadIdx.x < o) red[threadIdx.x] += red[threadIdx.x + o];
        __syncthreads();
    }
    float rstd = rsqrtf(red[0] * (1.f / DD) + EPS_LN);
    for (int d = threadIdx.x; d < DD; d += 256) {
        float val = (row[d] - mu) * rstd * w[d] + bias[d];
        __half h = __float2half_rn(val);
        g_act1[(size_t)bt * DD + d] = h;
        g_act2[(size_t)bt * DD + d] = __float2half_rn(val - __half2float(h));
    }
}

// ---------------- fused attention: scores + global max (grid barrier) + AV ----
__global__ void __launch_bounds__(256)
k_attn(int layer) {
    int bh = blockIdx.x;
    int h = bh % NHD, b = bh / NHD;
    __shared__ float4 Q4[NTOK][17];   // reused for V after scores
    __shared__ float4 K4[NTOK][17];
    __shared__ float Psh[NTOK][77];
    __shared__ float msh[NTOK];
    __shared__ float wred[8];
    __shared__ float rsum[NTOK];
    __shared__ float sh_gmx;
    int tid = threadIdx.x;
    const float4* qkv4 = (const float4*)g_qkv;
    for (int idx = tid; idx < NTOK * 16; idx += 256) {
        int r = idx >> 4, d4 = idx & 15;
        size_t base = (size_t)(b * NTOK + r) * (3 * DD / 4) + h * 16 + d4;
        Q4[r][d4] = qkv4[base];
        K4[r][d4] = qkv4[base + DD / 4];
    }
    for (int i = tid; i < NTOK; i += 256) msh[i] = g_m[b * NTOK + i];
    __syncthreads();
    int w = tid >> 5, lane = tid & 31;
    float lmax = -3.4e38f;
    for (int n = w; n < NTOK; n += 8) {
        float mn = msh[n];
        for (int m = lane; m < NTOK; m += 32) {
            float dot = 0.f;
            #pragma unroll
            for (int d4 = 0; d4 < 16; d4++) {
                float4 q = Q4[n][d4];
                float4 k = K4[m][d4];
                dot = fmaf(q.x, k.x, dot);
                dot = fmaf(q.y, k.y, dot);
                dot = fmaf(q.z, k.z, dot);
                dot = fmaf(q.w, k.w, dot);
            }
            float logit = dot * SCALE;
            if (mn * msh[m] == 0.f) logit = -INFINITY;
            else lmax = fmaxf(lmax, logit);
            Psh[n][m] = logit;
        }
    }
    #pragma unroll
    for (int o = 16; o > 0; o >>= 1)
        lmax = fmaxf(lmax, __shfl_xor_sync(0xffffffffu, lmax, o));
    if (lane == 0) wred[w] = lmax;
    __syncthreads();
    if (tid == 0) {
        float bm = wred[0];
        #pragma unroll
        for (int i = 1; i < 8; i++) bm = fmaxf(bm, wred[i]);
        if (bm > -3.3e38f) atomicMax(&g_gmax, fenc(bm));
        __threadfence();
        atomicAdd(&g_cnt, 1u);
    }
    __syncthreads();   // scores done: safe to overwrite Q4 with V
    for (int idx = tid; idx < NTOK * 16; idx += 256) {
        int r = idx >> 4, d4 = idx & 15;
        Q4[r][d4] = qkv4[(size_t)(b * NTOK + r) * (3 * DD / 4) + 2 * DD / 4 + h * 16 + d4];
    }
    if (tid == 0) {
        unsigned target = 192u * (unsigned)(layer + 1);
        while (atomicAdd(&g_cnt, 0u) < target) { }
        sh_gmx = fdec(atomicAdd(&g_gmax, 0u));
    }
    __syncthreads();
    float gmx = sh_gmx;
    for (int n = w; n < NTOK; n += 8) {
        float s = 0.f;
        for (int m = lane; m < NTOK; m += 32) {
            float e = expf(Psh[n][m] - gmx);
            Psh[n][m] = e;
            s += e;
        }
        #pragma unroll
        for (int o = 16; o > 0; o >>= 1) s += __shfl_xor_sync(0xffffffffu, s, o);
        if (lane == 0) rsum[n] = s;
    }
    __syncthreads();
    int d4 = lane & 15, par = lane >> 4;
    for (int n = w; n < NTOK; n += 8) {
        float inv = 1.f / (rsum[n] + 1e-9f);
        float4 acc = make_float4(0.f, 0.f, 0.f, 0.f);
        for (int m = par; m < NTOK; m += 2) {
            float p = Psh[n][m];
            float4 v = Q4[m][d4];
            acc.x = fmaf(p, v.x, acc.x);
            acc.y = fmaf(p, v.y, acc.y);
            acc.z = fmaf(p, v.z, acc.z);
            acc.w = fmaf(p, v.w, acc.w);
        }
        acc.x += __shfl_down_sync(0xffffffffu, acc.x, 16);
        acc.y += __shfl_down_sync(0xffffffffu, acc.y, 16);
        acc.z += __shfl_down_sync(0xffffffffu, acc.z, 16);
        acc.w += __shfl_down_sync(0xffffffffu, acc.w, 16);
        if (par == 0) {
            size_t o2 = (size_t)(b * NTOK + n) * DD + h * HD + d4 * 4;
            float vals[4] = {acc.x * inv, acc.y * inv, acc.z * inv, acc.w * inv};
            float r0, r1, r2, r3;
            uint32_t m1 = packh_big(vals[0], vals[1], r0, r1);
            uint32_t m2 = packh_big(vals[2], vals[3], r2, r3);
            *(uint2*)&g_act1[o2] = make_uint2(m1, m2);
            *(uint2*)&g_act2[o2] = make_uint2(packh(r0, r1), packh(r2, r3));
        }
    }
}

// ---------------- launch -----------------------------------------------------
extern "C" void kernel_launch(void* const* d_in, const int* in_sizes, int n_in,
                              void* d_out, int out_size) {
    const float* x         = (const float*)d_in[0];
    const float* attn_mask = (const float*)d_in[1];
    const int*   yids      = (const int*)  d_in[2];
    const float* noise     = (const float*)d_in[3];
    const float* conv_w    = (const float*)d_in[4];
    const float* conv_b    = (const float*)d_in[5];
    const float* pex       = (const float*)d_in[6];
    const float* ytab      = (const float*)d_in[7];
    const float* cls       = (const float*)d_in[8];
    const float* qkv_w     = (const float*)d_in[9];
    const float* qkv_b     = (const float*)d_in[10];
    const float* proj_w    = (const float*)d_in[11];
    const float* proj_b    = (const float*)d_in[12];
    const float* ln1_w     = (const float*)d_in[13];
    const float* ln1_b     = (const float*)d_in[14];
    const float* ln2_w     = (const float*)d_in[15];
    const float* ln2_b     = (const float*)d_in[16];
    const float* fc1_w     = (const float*)d_in[17];
    const float* fc1_b     = (const float*)d_in[18];
    const float* fc2_w     = (const float*)d_in[19];
    const float* fc2_b     = (const float*)d_in[20];
    const float* norm_w    = (const float*)d_in[21];
    const float* norm_b    = (const float*)d_in[22];
    float* out = (float*)d_out;

    float *carry, *qkv;
    __half *act1, *act2, *hid1, *hid2, *wq, *wp, *w1, *w2;
    cudaGetSymbolAddress((void**)&carry, g_carry);
    cudaGetSymbolAddress((void**)&qkv,   g_qkv);
    cudaGetSymbolAddress((void**)&act1,  g_act1);
    cudaGetSymbolAddress((void**)&act2,  g_act2);
    cudaGetSymbolAddress((void**)&hid1,  g_hid1);
    cudaGetSymbolAddress((void**)&hid2,  g_hid2);
    cudaGetSymbolAddress((void**)&wq,    g_wq);
    cudaGetSymbolAddress((void**)&wp,    g_wp);
    cudaGetSymbolAddress((void**)&w1,    g_w1);
    cudaGetSymbolAddress((void**)&w2,    g_w2);

    const int SM192 = 3 * (256 + 192) * 80;  // 107520 (qkv, TERMS=2)
    const int SM128 = 3 * (256 + 128) * 80;  // 92160  (fc1, TERMS=2)
    const int SM64  = 4 * (128 + 64)  * 80;  // 61440  (proj/fc2, TERMS=1)
    cudaFuncSetAttribute(k_gemm_f16<192, 0, 3, 1, 0, 2>, cudaFuncAttributeMaxDynamicSharedMemorySize, SM192);
    cudaFuncSetAttribute(k_gemm_f16<128, 1, 3, 2, 0, 2>, cudaFuncAttributeMaxDynamicSharedMemorySize, SM128);
    cudaFuncSetAttribute(k_gemm_f16<64, 2, 4, 2, 1, 1>,  cudaFuncAttributeMaxDynamicSharedMemorySize, SM64);
    cudaFuncSetAttribute(k_gemm_f16<64, 2, 4, 2, 2, 1>,  cudaFuncAttributeMaxDynamicSharedMemorySize, SM64);

    const int MT = M_PAD / 128;  // 10

    k_split_all<<<4096, 256>>>((const float4*)qkv_w, (const float4*)proj_w,
                               (const float4*)fc1_w, (const float4*)fc2_w);
    k_patchsel<<<BB * LL + BB, 256>>>(x, attn_mask, yids, conv_w, conv_b, pex, ytab, noise);
    k_gather_ln<<<MROWS, 256>>>(cls, pex, ln1_w, ln1_b);

    for (int l = 0; l < DEPTH; l++) {
        const float* qb  = qkv_b  + (size_t)l * 3 * DD;
        const float* pb  = proj_b + (size_t)l * DD;
        const float* l2w = ln2_w + l * DD; const float* l2b = ln2_b + l * DD;
        const float* f1b = fc1_b + (size_t)l * MLPD;
        const float* f2b = fc2_b + (size_t)l * DD;
        __half* lwq = wq + (size_t)l * 3 * DD * DD;
        __half* lwp = wp + (size_t)l * DD * DD;
        __half* lw1 = w1 + (size_t)l * MLPD * DD;
        __half* lw2 = w2 + (size_t)l * DD * MLPD;

        k_gemm_f16<192, 0, 3, 1, 0, 2><<<dim3(3 * DD / 192, MT), 256, SM192>>>(
            act1, act2, lwq, qb, nullptr, qkv, nullptr, nullptr, 3 * DD, DD,
            nullptr, nullptr, nullptr, 0);
        k_attn<<<BB * NHD, 256>>>(l);
        // proj (single-term act) + fused LN2 (split fp16 out for fc1)
        k_gemm_f16<64, 2, 4, 2, 1, 1><<<dim3(DD / 64, MT), 256, SM64>>>(
            act1, nullptr, lwp, pb, carry, carry, nullptr, nullptr, DD, DD,
            l2w, l2b, nullptr, 2 * l);
        k_gemm_f16<128, 1, 3, 2, 0, 2><<<dim3(MLPD / 128, MT), 256, SM128>>>(
            act1, act2, lw1, f1b, nullptr, nullptr, hid1, hid2, MLPD, DD,
            nullptr, nullptr, nullptr, 0);
        if (l < DEPTH - 1) {
            const float* n1w = ln1_w + (l + 1) * DD;
            const float* n1b = ln1_b + (l + 1) * DD;
            k_gemm_f16<64, 2, 4, 2, 1, 1><<<dim3(DD / 64, MT), 256, SM64>>>(
                hid1, nullptr, lw2, f2b, carry, carry, nullptr, nullptr, DD, MLPD,
                n1w, n1b, nullptr, 2 * l + 1);
        } else {
            k_gemm_f16<64, 2, 4, 2, 2, 1><<<dim3(DD / 64, MT), 256, SM64>>>(
                hid1, nullptr, lw2, f2b, carry, carry, nullptr, nullptr, DD, MLPD,
                norm_w, norm_b, out, 2 * l + 1);
        }
    }
}